// round 4
// baseline (speedup 1.0000x reference)
#include <cuda_runtime.h>
#include <cuda_bf16.h>
#include <math.h>

#define NN 512
#define DD 384
#define EE 128
#define HH 8
#define CATD 1280
#define HID 768

static __device__ __constant__ float SCAL_SCALE = 0.14433756729740643f; // (3*16)^-0.5
static __device__ __constant__ float POINT_SCALE = 0.13608276348795434f; // (3*4*4.5)^-0.5
static __device__ __constant__ float PAIR_SCALE = 0.5773502691896258f;  // 3^-0.5

// scratch
__device__ float g_qs[NN*128];
__device__ float g_kkT[128*NN];   // [h*16+k][j]
__device__ float g_vs[NN*128];
__device__ float g_qp[NN*96];
__device__ float g_kpT[96*NN];    // [h*12+q][j]
__device__ float g_vp[NN*96];
__device__ float g_q2[HH*NN];
__device__ float g_k2[HH*NN];
__device__ float g_cat[(size_t)NN*CATD];
__device__ float g_t0[NN*DD];
__device__ float g_t1[NN*DD];
__device__ float g_t2[NN*DD];
__device__ float g_t3[NN*DD];
__device__ float g_x1[NN*DD];
__device__ float g_h1[NN*HID];
__device__ float g_h2[NN*HID];

// ---------------------------------------------------------------------------
// K1: projections (4 residues / block) + rigid frames + squared norms
// ---------------------------------------------------------------------------
__global__ void k_proj(const float* __restrict__ node,
                       const float* __restrict__ rot,
                       const float* __restrict__ trans,
                       const float* __restrict__ Wq_s, const float* __restrict__ Wk_s,
                       const float* __restrict__ Wv_s,
                       const float* __restrict__ Wq_p, const float* __restrict__ Wk_p,
                       const float* __restrict__ Wv_p) {
    int i0 = blockIdx.x * 4;
    int t = threadIdx.x; // 256
    __shared__ float x_s[4][DD];
    __shared__ float praw[4][288];
    __shared__ float pg[4][192];

    for (int idx = t; idx < 4*DD; idx += 256)
        x_s[idx/DD][idx%DD] = node[i0*DD + idx];
    __syncthreads();

    for (int idx = t; idx < 4*672; idx += 256) {
        int r = idx / 672, c = idx % 672;
        const float* W; int ld, cc;
        if (c < 384) { int m = c >> 7; cc = c & 127; ld = 128;
                       W = (m==0) ? Wq_s : (m==1) ? Wk_s : Wv_s; }
        else { int cp = c - 384; int m = cp / 96; cc = cp % 96; ld = 96;
               W = (m==0) ? Wq_p : (m==1) ? Wk_p : Wv_p; }
        float a = 0.f;
        #pragma unroll 8
        for (int k = 0; k < DD; k++) a += x_s[r][k] * W[k*ld + cc];
        int i = i0 + r;
        if (c < 128)      g_qs[i*128 + c] = a;
        else if (c < 256) g_kkT[(c-128)*NN + i] = a;
        else if (c < 384) g_vs[i*128 + (c-256)] = a;
        else              praw[r][c-384] = a;
    }
    __syncthreads();

    for (int idx = t; idx < 4*288; idx += 256) {
        int r = idx / 288, q = idx % 288;
        int m = q / 96, qq = q % 96;
        int hd = qq / 3, rr = qq % 3;
        int i = i0 + r;
        const float* R = rot + i*9;
        float v = trans[i*3 + rr];
        #pragma unroll
        for (int c = 0; c < 3; c++) v += praw[r][m*96 + hd*3 + c] * R[c*3 + rr];
        if (m == 0)      { g_qp[i*96 + qq] = v; pg[r][qq] = v; }
        else if (m == 1) { g_kpT[qq*NN + i] = v; pg[r][96 + qq] = v; }
        else               g_vp[i*96 + qq] = v;
    }
    __syncthreads();

    if (t < 64) {
        int r = t >> 4, m = (t >> 3) & 1, h = t & 7;
        int i = i0 + r;
        float s = 0.f;
        #pragma unroll
        for (int q = 0; q < 12; q++) { float v = pg[r][m*96 + h*12 + q]; s += v*v; }
        (m ? g_k2 : g_q2)[h*NN + i] = s;
    }
}

// ---------------------------------------------------------------------------
// K2: fused logits + online softmax + all consumers. One edge pass.
// Block per i, 256 threads = 8 warps, 8 chunks of 64 j.
// ---------------------------------------------------------------------------
__global__ void k_attn(const float* __restrict__ edge,
                       const float* __restrict__ Wb,
                       const float* __restrict__ bb,
                       const float* __restrict__ pw,
                       const float* __restrict__ rot,
                       const float* __restrict__ trans) {
    int i = blockIdx.x, t = threadIdx.x;
    int wv = t >> 5, lane = t & 31;

    __shared__ float4 edge_s[64*33];   // 33.8 KB; reused as reduction buffer
    __shared__ float4 wb4[32*8];
    __shared__ float lg[8*64];
    __shared__ float qs_s[128], qp_s[96];
    __shared__ float q2_s[8], cw_s[8], bb_s[8];
    __shared__ float m_s[8], s_s[8], scale_s[8], inv_s[8];
    __shared__ float pts_s[96];

    if (t < 128) qs_s[t] = g_qs[i*128 + t];
    else if (t < 224) qp_s[t-128] = g_qp[i*96 + (t-128)];
    else if (t < 232) {
        int h = t - 224;
        q2_s[h] = g_q2[h*NN + i];
        bb_s[h] = bb[h];
        cw_s[h] = 0.5f * POINT_SCALE * log1pf(__expf(pw[h]));
    }
    if (t < 8) { m_s[t] = -1e30f; s_s[t] = 0.f; }
    {
        int eg = t >> 3, h = t & 7;
        wb4[eg*8 + h] = make_float4(Wb[(eg*4+0)*8 + h], Wb[(eg*4+1)*8 + h],
                                    Wb[(eg*4+2)*8 + h], Wb[(eg*4+3)*8 + h]);
    }

    float4 acc[8];
    #pragma unroll
    for (int h = 0; h < 8; h++) acc[h] = make_float4(0.f,0.f,0.f,0.f);
    float rs_acc = 0.f, pt_acc = 0.f;

    int jl = t & 63, hA = t >> 6, hB = hA + 4;
    __syncthreads();

    for (int ch = 0; ch < 8; ch++) {
        int j0 = ch * 64;
        // 1. load edge chunk (coalesced)
        const float4* eg = (const float4*)(edge + ((size_t)i*NN + j0)*EE);
        #pragma unroll 8
        for (int idx = t; idx < 2048; idx += 256)
            edge_s[(idx >> 5)*33 + (idx & 31)] = eg[idx];
        __syncthreads();

        // 2. logits for this chunk (2 heads per thread)
        {
            float pA = 0.f, pB = 0.f;
            #pragma unroll
            for (int g = 0; g < 32; g++) {
                float4 ev = edge_s[jl*33 + g];
                float4 wA = wb4[g*8 + hA];
                float4 wB = wb4[g*8 + hB];
                pA += ev.x*wA.x + ev.y*wA.y + ev.z*wA.z + ev.w*wA.w;
                pB += ev.x*wB.x + ev.y*wB.y + ev.z*wB.z + ev.w*wB.w;
            }
            int j = j0 + jl;
            float sA = 0.f, sB = 0.f;
            #pragma unroll
            for (int k = 0; k < 16; k++) {
                sA += qs_s[hA*16 + k] * g_kkT[(hA*16 + k)*NN + j];
                sB += qs_s[hB*16 + k] * g_kkT[(hB*16 + k)*NN + j];
            }
            float cA = 0.f, cB = 0.f;
            #pragma unroll
            for (int k = 0; k < 12; k++) {
                cA += qp_s[hA*12 + k] * g_kpT[(hA*12 + k)*NN + j];
                cB += qp_s[hB*12 + k] * g_kpT[(hB*12 + k)*NN + j];
            }
            float dA = q2_s[hA] + g_k2[hA*NN + j] - 2.f*cA;
            float dB = q2_s[hB] + g_k2[hB*NN + j] - 2.f*cB;
            lg[hA*64 + jl] = SCAL_SCALE*sA - cw_s[hA]*dA + (pA + bb_s[hA])*PAIR_SCALE;
            lg[hB*64 + jl] = SCAL_SCALE*sB - cw_s[hB]*dB + (pB + bb_s[hB])*PAIR_SCALE;
        }
        __syncthreads();

        // 3. per-head online-softmax merge (warp w = head w)
        {
            float v1 = lg[wv*64 + lane], v2 = lg[wv*64 + lane + 32];
            float mc = fmaxf(v1, v2);
            #pragma unroll
            for (int s = 16; s > 0; s >>= 1) mc = fmaxf(mc, __shfl_xor_sync(0xffffffffu, mc, s));
            float m_old = m_s[wv];
            float m_new = fmaxf(m_old, mc);
            float e1 = __expf(v1 - m_new), e2 = __expf(v2 - m_new);
            lg[wv*64 + lane]      = e1;
            lg[wv*64 + lane + 32] = e2;
            float cs = e1 + e2;
            #pragma unroll
            for (int s = 16; s > 0; s >>= 1) cs += __shfl_xor_sync(0xffffffffu, cs, s);
            if (lane == 0) {
                float scl = __expf(m_old - m_new);
                m_s[wv] = m_new;
                scale_s[wv] = scl;
                s_s[wv] = s_s[wv]*scl + cs;
            }
        }
        __syncthreads();

        // 4. rp accumulate: warp wv covers j-slice [wv*8, wv*8+8)
        {
            #pragma unroll
            for (int h = 0; h < 8; h++) {
                float sc = scale_s[h];
                acc[h].x *= sc; acc[h].y *= sc; acc[h].z *= sc; acc[h].w *= sc;
            }
            #pragma unroll
            for (int jj = 0; jj < 8; jj++) {
                float4 ev = edge_s[(wv*8 + jj)*33 + lane];
                #pragma unroll
                for (int h = 0; h < 8; h++) {
                    float p = lg[h*64 + wv*8 + jj];
                    acc[h].x += ev.x*p; acc[h].y += ev.y*p;
                    acc[h].z += ev.z*p; acc[h].w += ev.w*p;
                }
            }
        }
        // 5. rs / pts accumulate
        if (t < 128) {
            int c = t, h = c >> 4;
            rs_acc *= scale_s[h];
            #pragma unroll 8
            for (int j = 0; j < 64; j++)
                rs_acc += lg[h*64 + j] * g_vs[(size_t)(j0 + j)*128 + c];
        } else if (t < 224) {
            int q = t - 128, h = q / 12;
            pt_acc *= scale_s[h];
            #pragma unroll 8
            for (int j = 0; j < 64; j++)
                pt_acc += lg[h*64 + j] * g_vp[(size_t)(j0 + j)*96 + q];
        }
        __syncthreads();
    }

    if (t < 8) inv_s[t] = 1.f / s_s[t];
    __syncthreads();

    float* cat = &g_cat[(size_t)i*CATD];
    float4* red4 = edge_s; // reuse

    if (wv >= 4) {
        #pragma unroll
        for (int h = 0; h < 8; h++) red4[((wv-4)*8 + h)*32 + lane] = acc[h];
    }
    __syncthreads();
    if (wv < 4) {
        #pragma unroll
        for (int h = 0; h < 8; h++) {
            float4 o = red4[(wv*8 + h)*32 + lane];
            acc[h].x += o.x; acc[h].y += o.y; acc[h].z += o.z; acc[h].w += o.w;
        }
    }
    __syncthreads();
    if (wv < 4) {
        #pragma unroll
        for (int h = 0; h < 8; h++) red4[(wv*8 + h)*32 + lane] = acc[h];
    }
    __syncthreads();
    {
        int h = t >> 5, eg2 = t & 31;
        float4 s0 = red4[(0*8 + h)*32 + eg2];
        float4 s1 = red4[(1*8 + h)*32 + eg2];
        float4 s2 = red4[(2*8 + h)*32 + eg2];
        float4 s3 = red4[(3*8 + h)*32 + eg2];
        float iv = inv_s[h];
        float4 s = make_float4((s0.x+s1.x+s2.x+s3.x)*iv, (s0.y+s1.y+s2.y+s3.y)*iv,
                               (s0.z+s1.z+s2.z+s3.z)*iv, (s0.w+s1.w+s2.w+s3.w)*iv);
        ((float4*)(cat + 256))[h*32 + eg2] = s;
    }
    if (t < 128) cat[t] = rs_acc * inv_s[t >> 4];
    else if (t < 224) { int q = t - 128; pts_s[q] = pt_acc * inv_s[q / 12]; }
    __syncthreads();

    if (t < 32) {
        int base = t * 3;
        float T0 = trans[i*3], T1 = trans[i*3+1], T2 = trans[i*3+2];
        float x0 = pts_s[base] - T0, x1 = pts_s[base+1] - T1, x2 = pts_s[base+2] - T2;
        const float* R = &rot[i*9];
        float l0 = x0*R[0] + x1*R[1] + x2*R[2];
        float l1 = x0*R[3] + x1*R[4] + x2*R[5];
        float l2 = x0*R[6] + x1*R[7] + x2*R[8];
        cat[128 + base]     = l0;
        cat[128 + base + 1] = l1;
        cat[128 + base + 2] = l2;
        cat[224 + t] = sqrtf(l0*l0 + l1*l1 + l2*l2 + 1e-8f);
    }
}

// ---------------------------------------------------------------------------
// Register-blocked GEMM: 32x32 tile, BK=32, 128 threads, 2x4 micro.
// blockIdx.z selects K-slice (split-K up to 4); partial z writes to Yz.
// ---------------------------------------------------------------------------
template<int LDX, int NC, bool RELU>
__global__ void k_gemm(const float* __restrict__ X, const float* __restrict__ W,
                       const float* __restrict__ bias,
                       float* __restrict__ Y0, float* __restrict__ Y1,
                       float* __restrict__ Y2, float* __restrict__ Y3, int klen) {
    int r0 = blockIdx.x * 32, c0 = blockIdx.y * 32;
    int z = blockIdx.z;
    int kbase = z * klen;
    float* Y = (z == 0) ? Y0 : (z == 1) ? Y1 : (z == 2) ? Y2 : Y3;
    int t = threadIdx.x;
    __shared__ float Xs[32][33];
    __shared__ float Ws[32][36];

    int tx = t & 7, ty = t >> 3;
    int lrow = t >> 3, lkq = t & 7;

    float acc[2][4];
    #pragma unroll
    for (int a = 0; a < 2; a++)
        #pragma unroll
        for (int b = 0; b < 4; b++) acc[a][b] = 0.f;

    for (int kc = 0; kc < klen; kc += 32) {
        int kg = kbase + kc;
        #pragma unroll
        for (int rr = 0; rr < 2; rr++) {
            int row = lrow + rr*16;
            float4 v = *(const float4*)&X[(size_t)(r0 + row)*LDX + kg + lkq*4];
            Xs[lkq*4 + 0][row] = v.x;
            Xs[lkq*4 + 1][row] = v.y;
            Xs[lkq*4 + 2][row] = v.z;
            Xs[lkq*4 + 3][row] = v.w;
        }
        #pragma unroll
        for (int rr = 0; rr < 2; rr++) {
            int k = lrow + rr*16;
            float4 v = *(const float4*)&W[(size_t)(kg + k)*NC + c0 + lkq*4];
            *(float4*)&Ws[k][lkq*4] = v;
        }
        __syncthreads();

        #pragma unroll
        for (int k = 0; k < 32; k++) {
            float x0 = Xs[k][ty*2 + 0];
            float x1 = Xs[k][ty*2 + 1];
            float4 wv = *(const float4*)&Ws[k][tx*4];
            acc[0][0] += x0*wv.x; acc[0][1] += x0*wv.y;
            acc[0][2] += x0*wv.z; acc[0][3] += x0*wv.w;
            acc[1][0] += x1*wv.x; acc[1][1] += x1*wv.y;
            acc[1][2] += x1*wv.z; acc[1][3] += x1*wv.w;
        }
        __syncthreads();
    }

    #pragma unroll
    for (int a = 0; a < 2; a++) {
        int row = r0 + ty*2 + a;
        #pragma unroll
        for (int b = 0; b < 4; b++) {
            int col = c0 + tx*4 + b;
            float v = acc[a][b];
            if (z == 0) v += bias[col];
            if (RELU) v = fmaxf(v, 0.f);
            Y[(size_t)row*NC + col] = v;
        }
    }
}

// ---------------------------------------------------------------------------
// LayerNorm over 384 of (a+b+c+d). 128 threads, 3 elems each.
// ---------------------------------------------------------------------------
__global__ void k_ln4(const float* __restrict__ ia, const float* __restrict__ ib,
                      const float* __restrict__ ic, const float* __restrict__ id,
                      const float* __restrict__ g, const float* __restrict__ b,
                      float* __restrict__ out) {
    int i = blockIdx.x, t = threadIdx.x;
    __shared__ float red[128];
    float v0 = ia[i*DD+t]     + ib[i*DD+t]     + ic[i*DD+t]     + id[i*DD+t];
    float v1 = ia[i*DD+t+128] + ib[i*DD+t+128] + ic[i*DD+t+128] + id[i*DD+t+128];
    float v2 = ia[i*DD+t+256] + ib[i*DD+t+256] + ic[i*DD+t+256] + id[i*DD+t+256];
    red[t] = v0 + v1 + v2;
    __syncthreads();
    #pragma unroll
    for (int s = 64; s > 0; s >>= 1) { if (t < s) red[t] += red[t+s]; __syncthreads(); }
    float mu = red[0] * (1.f/384.f);
    __syncthreads();
    float d0 = v0-mu, d1 = v1-mu, d2 = v2-mu;
    red[t] = d0*d0 + d1*d1 + d2*d2;
    __syncthreads();
    #pragma unroll
    for (int s = 64; s > 0; s >>= 1) { if (t < s) red[t] += red[t+s]; __syncthreads(); }
    float inv = rsqrtf(red[0] * (1.f/384.f) + 1e-5f);
    out[i*DD + t]       = d0*inv*g[t]       + b[t];
    out[i*DD + t + 128] = d1*inv*g[t+128]   + b[t+128];
    out[i*DD + t + 256] = d2*inv*g[t+256]   + b[t+256];
}

// ---------------------------------------------------------------------------
extern "C" void kernel_launch(void* const* d_in, const int* in_sizes, int n_in,
                              void* d_out, int out_size) {
    const float* node  = (const float*)d_in[0];
    const float* edge  = (const float*)d_in[1];
    const float* rot   = (const float*)d_in[2];
    const float* trans = (const float*)d_in[3];
    const float* Wq_s = (const float*)d_in[5];
    const float* Wk_s = (const float*)d_in[6];
    const float* Wv_s = (const float*)d_in[7];
    const float* Wq_p = (const float*)d_in[8];
    const float* Wk_p = (const float*)d_in[9];
    const float* Wv_p = (const float*)d_in[10];
    const float* pw   = (const float*)d_in[11];
    const float* Wb   = (const float*)d_in[12];
    const float* bb   = (const float*)d_in[13];
    const float* Wo   = (const float*)d_in[14];
    const float* bo   = (const float*)d_in[15];
    const float* g1   = (const float*)d_in[16];
    const float* beta1= (const float*)d_in[17];
    const float* W1   = (const float*)d_in[18];
    const float* b1   = (const float*)d_in[19];
    const float* W2   = (const float*)d_in[20];
    const float* b2   = (const float*)d_in[21];
    const float* W3   = (const float*)d_in[22];
    const float* b3   = (const float*)d_in[23];
    const float* g2   = (const float*)d_in[24];
    const float* beta2= (const float*)d_in[25];
    float* out = (float*)d_out;

    float *p_cat, *p_t0, *p_t1, *p_t2, *p_t3, *p_x1, *p_h1, *p_h2;
    cudaGetSymbolAddress((void**)&p_cat, g_cat);
    cudaGetSymbolAddress((void**)&p_t0, g_t0);
    cudaGetSymbolAddress((void**)&p_t1, g_t1);
    cudaGetSymbolAddress((void**)&p_t2, g_t2);
    cudaGetSymbolAddress((void**)&p_t3, g_t3);
    cudaGetSymbolAddress((void**)&p_x1, g_x1);
    cudaGetSymbolAddress((void**)&p_h1, g_h1);
    cudaGetSymbolAddress((void**)&p_h2, g_h2);

    k_proj<<<128, 256>>>(node, rot, trans, Wq_s, Wk_s, Wv_s, Wq_p, Wk_p, Wv_p);
    k_attn<<<NN, 256>>>(edge, Wb, bb, pw, rot, trans);

    // Wo: split-K 4 x 320
    k_gemm<CATD, DD, false><<<dim3(16, 12, 4), 128>>>(p_cat, Wo, bo, p_t0, p_t1, p_t2, p_t3, 320);
    k_ln4<<<NN, 128>>>(p_t0, p_t1, p_t2, p_t3, g1, beta1, p_x1);
    // MLP
    k_gemm<DD, HID, true><<<dim3(16, 24, 1), 128>>>(p_x1, W1, b1, p_h1, p_h1, p_h1, p_h1, 384);
    k_gemm<HID, HID, true><<<dim3(16, 24, 1), 128>>>(p_h1, W2, b2, p_h2, p_h2, p_h2, p_h2, 768);
    // W3: split-K 4 x 192
    k_gemm<HID, DD, false><<<dim3(16, 12, 4), 128>>>(p_h2, W3, b3, p_t0, p_t1, p_t2, p_t3, 192);
    k_ln4<<<NN, 128>>>(p_t0, p_t1, p_t2, p_t3, g2, beta2, out);
}

// round 5
// speedup vs baseline: 1.0187x; 1.0187x over previous
#include <cuda_runtime.h>
#include <cuda_bf16.h>
#include <math.h>

#define NN 512
#define DD 384
#define EE 128
#define HH 8
#define CATD 1280
#define HID 768

static __device__ __constant__ float SCAL_SCALE = 0.14433756729740643f; // (3*16)^-0.5
static __device__ __constant__ float POINT_SCALE = 0.13608276348795434f; // (3*4*4.5)^-0.5
static __device__ __constant__ float PAIR_SCALE = 0.5773502691896258f;  // 3^-0.5

// scratch
__device__ float g_qs[NN*128];
__device__ float g_kkT[128*NN];   // [h*16+k][j]
__device__ float g_vs[NN*128];
__device__ float g_qp[NN*96];
__device__ float g_kpT[96*NN];    // [h*12+q][j]
__device__ float g_vp[NN*96];
__device__ float g_q2[HH*NN];
__device__ float g_k2[HH*NN];
__device__ float g_attn[(size_t)HH*NN*NN];
__device__ float g_rpp[(size_t)4*NN*1024];   // rp partials [jc][i][h*128+e]
__device__ float g_cat[(size_t)NN*CATD];
__device__ float g_t0[NN*DD];
__device__ float g_t1[NN*DD];
__device__ float g_t2[NN*DD];
__device__ float g_t3[NN*DD];
__device__ float g_x1[NN*DD];
__device__ float g_h1[NN*HID];
__device__ float g_h2[NN*HID];

// ---------------------------------------------------------------------------
// K1: projections (4 residues / block) + rigid frames + squared norms
// ---------------------------------------------------------------------------
__global__ void k_proj(const float* __restrict__ node,
                       const float* __restrict__ rot,
                       const float* __restrict__ trans,
                       const float* __restrict__ Wq_s, const float* __restrict__ Wk_s,
                       const float* __restrict__ Wv_s,
                       const float* __restrict__ Wq_p, const float* __restrict__ Wk_p,
                       const float* __restrict__ Wv_p) {
    int i0 = blockIdx.x * 4;
    int t = threadIdx.x; // 256
    __shared__ float x_s[4][DD];
    __shared__ float praw[4][288];
    __shared__ float pg[4][192];

    for (int idx = t; idx < 4*DD; idx += 256)
        x_s[idx/DD][idx%DD] = node[i0*DD + idx];
    __syncthreads();

    for (int idx = t; idx < 4*672; idx += 256) {
        int r = idx / 672, c = idx % 672;
        const float* W; int ld, cc;
        if (c < 384) { int m = c >> 7; cc = c & 127; ld = 128;
                       W = (m==0) ? Wq_s : (m==1) ? Wk_s : Wv_s; }
        else { int cp = c - 384; int m = cp / 96; cc = cp % 96; ld = 96;
               W = (m==0) ? Wq_p : (m==1) ? Wk_p : Wv_p; }
        float a = 0.f;
        #pragma unroll 8
        for (int k = 0; k < DD; k++) a += x_s[r][k] * W[k*ld + cc];
        int i = i0 + r;
        if (c < 128)      g_qs[i*128 + c] = a;
        else if (c < 256) g_kkT[(c-128)*NN + i] = a;
        else if (c < 384) g_vs[i*128 + (c-256)] = a;
        else              praw[r][c-384] = a;
    }
    __syncthreads();

    for (int idx = t; idx < 4*288; idx += 256) {
        int r = idx / 288, q = idx % 288;
        int m = q / 96, qq = q % 96;
        int hd = qq / 3, rr = qq % 3;
        int i = i0 + r;
        const float* R = rot + i*9;
        float v = trans[i*3 + rr];
        #pragma unroll
        for (int c = 0; c < 3; c++) v += praw[r][m*96 + hd*3 + c] * R[c*3 + rr];
        if (m == 0)      { g_qp[i*96 + qq] = v; pg[r][qq] = v; }
        else if (m == 1) { g_kpT[qq*NN + i] = v; pg[r][96 + qq] = v; }
        else               g_vp[i*96 + qq] = v;
    }
    __syncthreads();

    if (t < 64) {
        int r = t >> 4, m = (t >> 3) & 1, h = t & 7;
        int i = i0 + r;
        float s = 0.f;
        #pragma unroll
        for (int q = 0; q < 12; q++) { float v = pg[r][m*96 + h*12 + q]; s += v*v; }
        (m ? g_k2 : g_q2)[h*NN + i] = s;
    }
}

// ---------------------------------------------------------------------------
// kA: logits for one 64-j chunk. grid (512, 8), 256 threads.
// ---------------------------------------------------------------------------
__global__ void k_logits(const float* __restrict__ edge,
                         const float* __restrict__ Wb,
                         const float* __restrict__ bb,
                         const float* __restrict__ pw) {
    int i = blockIdx.x, jc = blockIdx.y, j0 = jc * 64;
    int t = threadIdx.x; // 256
    __shared__ float qs_s[128], qp_s[96], q2_s[8], cw_s[8], bb_s[8];
    __shared__ float4 wb4[32*8];
    __shared__ float4 edge_s[64*33];

    if (t < 128) qs_s[t] = g_qs[i*128 + t];
    else if (t < 224) qp_s[t-128] = g_qp[i*96 + (t-128)];
    else if (t < 232) {
        int h = t - 224;
        q2_s[h] = g_q2[h*NN + i];
        bb_s[h] = bb[h];
        cw_s[h] = 0.5f * POINT_SCALE * log1pf(__expf(pw[h]));
    }
    {
        int eg = t >> 3, h = t & 7;
        wb4[eg*8 + h] = make_float4(Wb[(eg*4+0)*8 + h], Wb[(eg*4+1)*8 + h],
                                    Wb[(eg*4+2)*8 + h], Wb[(eg*4+3)*8 + h]);
    }
    {
        const float4* eg = (const float4*)(edge + ((size_t)i*NN + j0)*EE);
        #pragma unroll 8
        for (int idx = t; idx < 2048; idx += 256)
            edge_s[(idx >> 5)*33 + (idx & 31)] = eg[idx];
    }
    __syncthreads();

    int jl = t & 63, hA = t >> 6, hB = hA + 4;
    float pA = 0.f, pB = 0.f;
    #pragma unroll
    for (int g = 0; g < 32; g++) {
        float4 ev = edge_s[jl*33 + g];
        float4 wA = wb4[g*8 + hA];
        float4 wB = wb4[g*8 + hB];
        pA += ev.x*wA.x + ev.y*wA.y + ev.z*wA.z + ev.w*wA.w;
        pB += ev.x*wB.x + ev.y*wB.y + ev.z*wB.z + ev.w*wB.w;
    }
    int j = j0 + jl;
    float sA = 0.f, sB = 0.f;
    #pragma unroll
    for (int k = 0; k < 16; k++) {
        sA += qs_s[hA*16 + k] * g_kkT[(hA*16 + k)*NN + j];
        sB += qs_s[hB*16 + k] * g_kkT[(hB*16 + k)*NN + j];
    }
    float cA = 0.f, cB = 0.f;
    #pragma unroll
    for (int k = 0; k < 12; k++) {
        cA += qp_s[hA*12 + k] * g_kpT[(hA*12 + k)*NN + j];
        cB += qp_s[hB*12 + k] * g_kpT[(hB*12 + k)*NN + j];
    }
    float dA = q2_s[hA] + g_k2[hA*NN + j] - 2.f*cA;
    float dB = q2_s[hB] + g_k2[hB*NN + j] - 2.f*cB;
    g_attn[((size_t)hA*NN + i)*NN + j] =
        SCAL_SCALE*sA - cw_s[hA]*dA + (pA + bb_s[hA])*PAIR_SCALE;
    g_attn[((size_t)hB*NN + i)*NN + j] =
        SCAL_SCALE*sB - cw_s[hB]*dB + (pB + bb_s[hB])*PAIR_SCALE;
}

// ---------------------------------------------------------------------------
// kB: softmax over j. One block per (h,i) row.
// ---------------------------------------------------------------------------
__global__ void k_softmax() {
    size_t row = blockIdx.x;
    float* p = g_attn + row * NN;
    int t = threadIdx.x; // 256
    float a = p[t], b = p[t + 256];
    __shared__ float red[256];
    red[t] = fmaxf(a, b);
    __syncthreads();
    #pragma unroll
    for (int s = 128; s > 0; s >>= 1) {
        if (t < s) red[t] = fmaxf(red[t], red[t + s]);
        __syncthreads();
    }
    float M = red[0];
    __syncthreads();
    float ea = __expf(a - M), eb = __expf(b - M);
    red[t] = ea + eb;
    __syncthreads();
    #pragma unroll
    for (int s = 128; s > 0; s >>= 1) {
        if (t < s) red[t] += red[t + s];
        __syncthreads();
    }
    float inv = 1.f / red[0];
    p[t] = ea * inv;
    p[t + 256] = eb * inv;
}

// ---------------------------------------------------------------------------
// kC: rp partials for one 128-j chunk. grid (512, 4), 256 threads.
// ---------------------------------------------------------------------------
__global__ void k_rp(const float* __restrict__ edge) {
    int i = blockIdx.x, jc = blockIdx.y, j0 = jc * 128;
    int t = threadIdx.x;
    int e4 = t & 31, jg = t >> 5;
    __shared__ float lg_s[8*128];
    __shared__ float4 red4[4*8*32];

    for (int idx = t; idx < 1024; idx += 256)
        lg_s[idx] = g_attn[((size_t)(idx >> 7)*NN + i)*NN + j0 + (idx & 127)];
    __syncthreads();

    float4 acc[8];
    #pragma unroll
    for (int h = 0; h < 8; h++) acc[h] = make_float4(0.f,0.f,0.f,0.f);

    const float4* ep = (const float4*)(edge + ((size_t)i*NN + j0 + jg*16)*EE) + e4;
    #pragma unroll
    for (int jj = 0; jj < 16; jj++) {
        float4 ev = ep[(size_t)jj*32];
        #pragma unroll
        for (int h = 0; h < 8; h++) {
            float p = lg_s[h*128 + jg*16 + jj];
            acc[h].x += ev.x*p; acc[h].y += ev.y*p;
            acc[h].z += ev.z*p; acc[h].w += ev.w*p;
        }
    }
    if (jg >= 4) {
        #pragma unroll
        for (int h = 0; h < 8; h++) red4[((jg-4)*8 + h)*32 + e4] = acc[h];
    }
    __syncthreads();
    if (jg < 4) {
        #pragma unroll
        for (int h = 0; h < 8; h++) {
            float4 o = red4[(jg*8 + h)*32 + e4];
            acc[h].x += o.x; acc[h].y += o.y; acc[h].z += o.z; acc[h].w += o.w;
        }
    }
    __syncthreads();
    if (jg < 4) {
        #pragma unroll
        for (int h = 0; h < 8; h++) red4[(jg*8 + h)*32 + e4] = acc[h];
    }
    __syncthreads();
    {
        int h = t >> 5, e = t & 31;
        float4 s0 = red4[(0*8 + h)*32 + e];
        float4 s1 = red4[(1*8 + h)*32 + e];
        float4 s2 = red4[(2*8 + h)*32 + e];
        float4 s3 = red4[(3*8 + h)*32 + e];
        float4 s = make_float4(s0.x+s1.x+s2.x+s3.x, s0.y+s1.y+s2.y+s3.y,
                               s0.z+s1.z+s2.z+s3.z, s0.w+s1.w+s2.w+s3.w);
        ((float4*)(g_rpp + ((size_t)jc*NN + i)*1024))[h*32 + e] = s;
    }
}

// ---------------------------------------------------------------------------
// kD: rs / pts / norms + rp reduction -> cat. grid 512, 256 threads.
// ---------------------------------------------------------------------------
__global__ void k_assemble(const float* __restrict__ rot,
                           const float* __restrict__ trans) {
    int i = blockIdx.x, t = threadIdx.x;
    __shared__ float at_s[8*512];
    __shared__ float pts_s[96];

    for (int idx = t; idx < 4096; idx += 256)
        at_s[idx] = g_attn[((size_t)(idx >> 9)*NN + i)*NN + (idx & 511)];
    __syncthreads();

    float* cat = &g_cat[(size_t)i*CATD];

    if (t < 128) {
        int c = t, h = c >> 4;
        float a = 0.f;
        #pragma unroll 8
        for (int j = 0; j < 512; j++)
            a += at_s[h*512 + j] * g_vs[(size_t)j*128 + c];
        cat[c] = a;
    } else if (t < 224) {
        int q = t - 128, h = q / 12;
        float a = 0.f;
        #pragma unroll 8
        for (int j = 0; j < 512; j++)
            a += at_s[h*512 + j] * g_vp[(size_t)j*96 + q];
        pts_s[q] = a;
    }
    for (int o = t; o < 1024; o += 256) {
        cat[256 + o] = g_rpp[((size_t)0*NN + i)*1024 + o]
                     + g_rpp[((size_t)1*NN + i)*1024 + o]
                     + g_rpp[((size_t)2*NN + i)*1024 + o]
                     + g_rpp[((size_t)3*NN + i)*1024 + o];
    }
    __syncthreads();

    if (t < 32) {
        int base = t * 3;
        float T0 = trans[i*3], T1 = trans[i*3+1], T2 = trans[i*3+2];
        float x0 = pts_s[base] - T0, x1 = pts_s[base+1] - T1, x2 = pts_s[base+2] - T2;
        const float* R = &rot[i*9];
        float l0 = x0*R[0] + x1*R[1] + x2*R[2];
        float l1 = x0*R[3] + x1*R[4] + x2*R[5];
        float l2 = x0*R[6] + x1*R[7] + x2*R[8];
        cat[128 + base]     = l0;
        cat[128 + base + 1] = l1;
        cat[128 + base + 2] = l2;
        cat[224 + t] = sqrtf(l0*l0 + l1*l1 + l2*l2 + 1e-8f);
    }
}

// ---------------------------------------------------------------------------
// Register-blocked GEMM: 32x32 tile, BK=32, 128 threads, 2x4 micro.
// blockIdx.z selects K-slice (split-K up to 4); partial z writes to Yz.
// ---------------------------------------------------------------------------
template<int LDX, int NC, bool RELU>
__global__ void k_gemm(const float* __restrict__ X, const float* __restrict__ W,
                       const float* __restrict__ bias,
                       float* __restrict__ Y0, float* __restrict__ Y1,
                       float* __restrict__ Y2, float* __restrict__ Y3, int klen) {
    int r0 = blockIdx.x * 32, c0 = blockIdx.y * 32;
    int z = blockIdx.z;
    int kbase = z * klen;
    float* Y = (z == 0) ? Y0 : (z == 1) ? Y1 : (z == 2) ? Y2 : Y3;
    int t = threadIdx.x;
    __shared__ float Xs[32][33];
    __shared__ float Ws[32][36];

    int tx = t & 7, ty = t >> 3;
    int lrow = t >> 3, lkq = t & 7;

    float acc[2][4];
    #pragma unroll
    for (int a = 0; a < 2; a++)
        #pragma unroll
        for (int b = 0; b < 4; b++) acc[a][b] = 0.f;

    for (int kc = 0; kc < klen; kc += 32) {
        int kg = kbase + kc;
        #pragma unroll
        for (int rr = 0; rr < 2; rr++) {
            int row = lrow + rr*16;
            float4 v = *(const float4*)&X[(size_t)(r0 + row)*LDX + kg + lkq*4];
            Xs[lkq*4 + 0][row] = v.x;
            Xs[lkq*4 + 1][row] = v.y;
            Xs[lkq*4 + 2][row] = v.z;
            Xs[lkq*4 + 3][row] = v.w;
        }
        #pragma unroll
        for (int rr = 0; rr < 2; rr++) {
            int k = lrow + rr*16;
            float4 v = *(const float4*)&W[(size_t)(kg + k)*NC + c0 + lkq*4];
            *(float4*)&Ws[k][lkq*4] = v;
        }
        __syncthreads();

        #pragma unroll
        for (int k = 0; k < 32; k++) {
            float x0 = Xs[k][ty*2 + 0];
            float x1 = Xs[k][ty*2 + 1];
            float4 wv = *(const float4*)&Ws[k][tx*4];
            acc[0][0] += x0*wv.x; acc[0][1] += x0*wv.y;
            acc[0][2] += x0*wv.z; acc[0][3] += x0*wv.w;
            acc[1][0] += x1*wv.x; acc[1][1] += x1*wv.y;
            acc[1][2] += x1*wv.z; acc[1][3] += x1*wv.w;
        }
        __syncthreads();
    }

    #pragma unroll
    for (int a = 0; a < 2; a++) {
        int row = r0 + ty*2 + a;
        #pragma unroll
        for (int b = 0; b < 4; b++) {
            int col = c0 + tx*4 + b;
            float v = acc[a][b];
            if (z == 0) v += bias[col];
            if (RELU) v = fmaxf(v, 0.f);
            Y[(size_t)row*NC + col] = v;
        }
    }
}

// ---------------------------------------------------------------------------
// LayerNorm over 384 of (a+b+c+d). 128 threads, 3 elems each.
// ---------------------------------------------------------------------------
__global__ void k_ln4(const float* __restrict__ ia, const float* __restrict__ ib,
                      const float* __restrict__ ic, const float* __restrict__ id,
                      const float* __restrict__ g, const float* __restrict__ b,
                      float* __restrict__ out) {
    int i = blockIdx.x, t = threadIdx.x;
    __shared__ float red[128];
    float v0 = ia[i*DD+t]     + ib[i*DD+t]     + ic[i*DD+t]     + id[i*DD+t];
    float v1 = ia[i*DD+t+128] + ib[i*DD+t+128] + ic[i*DD+t+128] + id[i*DD+t+128];
    float v2 = ia[i*DD+t+256] + ib[i*DD+t+256] + ic[i*DD+t+256] + id[i*DD+t+256];
    red[t] = v0 + v1 + v2;
    __syncthreads();
    #pragma unroll
    for (int s = 64; s > 0; s >>= 1) { if (t < s) red[t] += red[t+s]; __syncthreads(); }
    float mu = red[0] * (1.f/384.f);
    __syncthreads();
    float d0 = v0-mu, d1 = v1-mu, d2 = v2-mu;
    red[t] = d0*d0 + d1*d1 + d2*d2;
    __syncthreads();
    #pragma unroll
    for (int s = 64; s > 0; s >>= 1) { if (t < s) red[t] += red[t+s]; __syncthreads(); }
    float inv = rsqrtf(red[0] * (1.f/384.f) + 1e-5f);
    out[i*DD + t]       = d0*inv*g[t]       + b[t];
    out[i*DD + t + 128] = d1*inv*g[t+128]   + b[t+128];
    out[i*DD + t + 256] = d2*inv*g[t+256]   + b[t+256];
}

// ---------------------------------------------------------------------------
extern "C" void kernel_launch(void* const* d_in, const int* in_sizes, int n_in,
                              void* d_out, int out_size) {
    const float* node  = (const float*)d_in[0];
    const float* edge  = (const float*)d_in[1];
    const float* rot   = (const float*)d_in[2];
    const float* trans = (const float*)d_in[3];
    const float* Wq_s = (const float*)d_in[5];
    const float* Wk_s = (const float*)d_in[6];
    const float* Wv_s = (const float*)d_in[7];
    const float* Wq_p = (const float*)d_in[8];
    const float* Wk_p = (const float*)d_in[9];
    const float* Wv_p = (const float*)d_in[10];
    const float* pw   = (const float*)d_in[11];
    const float* Wb   = (const float*)d_in[12];
    const float* bb   = (const float*)d_in[13];
    const float* Wo   = (const float*)d_in[14];
    const float* bo   = (const float*)d_in[15];
    const float* g1   = (const float*)d_in[16];
    const float* beta1= (const float*)d_in[17];
    const float* W1   = (const float*)d_in[18];
    const float* b1   = (const float*)d_in[19];
    const float* W2   = (const float*)d_in[20];
    const float* b2   = (const float*)d_in[21];
    const float* W3   = (const float*)d_in[22];
    const float* b3   = (const float*)d_in[23];
    const float* g2   = (const float*)d_in[24];
    const float* beta2= (const float*)d_in[25];
    float* out = (float*)d_out;

    float *p_cat, *p_t0, *p_t1, *p_t2, *p_t3, *p_x1, *p_h1, *p_h2;
    cudaGetSymbolAddress((void**)&p_cat, g_cat);
    cudaGetSymbolAddress((void**)&p_t0, g_t0);
    cudaGetSymbolAddress((void**)&p_t1, g_t1);
    cudaGetSymbolAddress((void**)&p_t2, g_t2);
    cudaGetSymbolAddress((void**)&p_t3, g_t3);
    cudaGetSymbolAddress((void**)&p_x1, g_x1);
    cudaGetSymbolAddress((void**)&p_h1, g_h1);
    cudaGetSymbolAddress((void**)&p_h2, g_h2);

    k_proj<<<128, 256>>>(node, rot, trans, Wq_s, Wk_s, Wv_s, Wq_p, Wk_p, Wv_p);
    k_logits<<<dim3(NN, 8), 256>>>(edge, Wb, bb, pw);
    k_softmax<<<HH*NN, 256>>>();
    k_rp<<<dim3(NN, 4), 256>>>(edge);
    k_assemble<<<NN, 256>>>(rot, trans);

    // Wo: split-K 4 x 320
    k_gemm<CATD, DD, false><<<dim3(16, 12, 4), 128>>>(p_cat, Wo, bo, p_t0, p_t1, p_t2, p_t3, 320);
    k_ln4<<<NN, 128>>>(p_t0, p_t1, p_t2, p_t3, g1, beta1, p_x1);
    // MLP
    k_gemm<DD, HID, true><<<dim3(16, 24, 1), 128>>>(p_x1, W1, b1, p_h1, p_h1, p_h1, p_h1, 384);
    k_gemm<HID, HID, true><<<dim3(16, 24, 1), 128>>>(p_h1, W2, b2, p_h2, p_h2, p_h2, p_h2, 768);
    // W3: split-K 4 x 192
    k_gemm<HID, DD, false><<<dim3(16, 12, 4), 128>>>(p_h2, W3, b3, p_t0, p_t1, p_t2, p_t3, 192);
    k_ln4<<<NN, 128>>>(p_t0, p_t1, p_t2, p_t3, g2, beta2, out);
}

// round 6
// speedup vs baseline: 2.3801x; 2.3365x over previous
#include <cuda_runtime.h>
#include <cuda_bf16.h>
#include <math.h>

#define NN 512
#define DD 384
#define EE 128
#define HH 8
#define CATD 1280
#define HID 768
#define PCOLS 672

static __device__ __constant__ float SCAL_SCALE = 0.14433756729740643f; // (3*16)^-0.5
static __device__ __constant__ float POINT_SCALE = 0.13608276348795434f; // (3*4*4.5)^-0.5
static __device__ __constant__ float PAIR_SCALE = 0.5773502691896258f;  // 3^-0.5

// scratch
__device__ float g_Wall[DD*PCOLS];
__device__ float g_zero[PCOLS];
__device__ float g_proj[NN*PCOLS];
__device__ float g_qs[NN*128];
__device__ float g_kkT[128*NN];   // [h*16+k][j]
__device__ float g_vs[NN*128];
__device__ float g_qp[NN*96];
__device__ float g_kpT[96*NN];    // [h*12+q][j]
__device__ float g_vp[NN*96];
__device__ float g_q2[HH*NN];
__device__ float g_k2[HH*NN];
__device__ float g_attn[(size_t)HH*NN*NN];
__device__ float g_rpp[(size_t)8*NN*1024];   // rp partials [jc][i][h*128+e]
__device__ float g_cat[(size_t)NN*CATD];
__device__ float g_t0[NN*DD];
__device__ float g_t1[NN*DD];
__device__ float g_t2[NN*DD];
__device__ float g_t3[NN*DD];
__device__ float g_x1[NN*DD];
__device__ float g_h1[NN*HID];
__device__ float g_h2[NN*HID];

// ---------------------------------------------------------------------------
// K0: pack projection weights into one [384 x 672] matrix + zero bias
// ---------------------------------------------------------------------------
__global__ void k_packW(const float* __restrict__ Wq_s, const float* __restrict__ Wk_s,
                        const float* __restrict__ Wv_s,
                        const float* __restrict__ Wq_p, const float* __restrict__ Wk_p,
                        const float* __restrict__ Wv_p) {
    int idx = blockIdx.x * 256 + threadIdx.x;
    if (idx < PCOLS) g_zero[idx] = 0.f;
    if (idx >= DD*PCOLS) return;
    int r = idx / PCOLS, c = idx % PCOLS;
    float v;
    if (c < 128)      v = Wq_s[r*128 + c];
    else if (c < 256) v = Wk_s[r*128 + (c-128)];
    else if (c < 384) v = Wv_s[r*128 + (c-256)];
    else if (c < 480) v = Wq_p[r*96 + (c-384)];
    else if (c < 576) v = Wk_p[r*96 + (c-480)];
    else              v = Wv_p[r*96 + (c-576)];
    g_Wall[idx] = v;
}

// ---------------------------------------------------------------------------
// K_post: scatter proj results, rigid transforms, q2/k2. One block per i.
// ---------------------------------------------------------------------------
__global__ void k_post(const float* __restrict__ rot,
                       const float* __restrict__ trans) {
    int i = blockIdx.x, t = threadIdx.x; // 128
    __shared__ float pg[192];
    const float* pr = &g_proj[i*PCOLS];

    // scalar outputs
    float a = pr[t];
    g_qs[i*128 + t] = a;
    g_kkT[t*NN + i] = pr[128 + t];
    g_vs[i*128 + t] = pr[256 + t];

    // rigid transforms: 288 outputs, 128 threads
    const float* R = &rot[i*9];
    float T[3] = {trans[i*3], trans[i*3+1], trans[i*3+2]};
    for (int q = t; q < 288; q += 128) {
        int m = q / 96, qq = q % 96;
        int hd = qq / 3, rr = qq % 3;
        float v = T[rr];
        #pragma unroll
        for (int c = 0; c < 3; c++) v += pr[384 + m*96 + hd*3 + c] * R[c*3 + rr];
        if (m == 0)      { g_qp[i*96 + qq] = v; pg[qq] = v; }
        else if (m == 1) { g_kpT[qq*NN + i] = v; pg[96 + qq] = v; }
        else               g_vp[i*96 + qq] = v;
    }
    __syncthreads();

    if (t < 16) {
        int m = t >> 3, h = t & 7;
        float s = 0.f;
        #pragma unroll
        for (int q = 0; q < 12; q++) { float v = pg[m*96 + h*12 + q]; s += v*v; }
        (m ? g_k2 : g_q2)[h*NN + i] = s;
    }
}

// ---------------------------------------------------------------------------
// kA: logits for one 64-j chunk. grid (512, 8), 256 threads.  <-- launch #4
// ---------------------------------------------------------------------------
__global__ void k_logits(const float* __restrict__ edge,
                         const float* __restrict__ Wb,
                         const float* __restrict__ bb,
                         const float* __restrict__ pw) {
    int i = blockIdx.x, jc = blockIdx.y, j0 = jc * 64;
    int t = threadIdx.x; // 256
    __shared__ float qs_s[128], qp_s[96], q2_s[8], cw_s[8], bb_s[8];
    __shared__ float4 wb4[32*8];
    __shared__ float4 edge_s[64*33];

    if (t < 128) qs_s[t] = g_qs[i*128 + t];
    else if (t < 224) qp_s[t-128] = g_qp[i*96 + (t-128)];
    else if (t < 232) {
        int h = t - 224;
        q2_s[h] = g_q2[h*NN + i];
        bb_s[h] = bb[h];
        cw_s[h] = 0.5f * POINT_SCALE * log1pf(__expf(pw[h]));
    }
    {
        int eg = t >> 3, h = t & 7;
        wb4[eg*8 + h] = make_float4(Wb[(eg*4+0)*8 + h], Wb[(eg*4+1)*8 + h],
                                    Wb[(eg*4+2)*8 + h], Wb[(eg*4+3)*8 + h]);
    }
    {
        const float4* eg = (const float4*)(edge + ((size_t)i*NN + j0)*EE);
        #pragma unroll 8
        for (int idx = t; idx < 2048; idx += 256)
            edge_s[(idx >> 5)*33 + (idx & 31)] = eg[idx];
    }
    __syncthreads();

    int jl = t & 63, hA = t >> 6, hB = hA + 4;
    float pA = 0.f, pB = 0.f;
    #pragma unroll
    for (int g = 0; g < 32; g++) {
        float4 ev = edge_s[jl*33 + g];
        float4 wA = wb4[g*8 + hA];
        float4 wB = wb4[g*8 + hB];
        pA += ev.x*wA.x + ev.y*wA.y + ev.z*wA.z + ev.w*wA.w;
        pB += ev.x*wB.x + ev.y*wB.y + ev.z*wB.z + ev.w*wB.w;
    }
    int j = j0 + jl;
    float sA = 0.f, sB = 0.f;
    #pragma unroll
    for (int k = 0; k < 16; k++) {
        sA += qs_s[hA*16 + k] * g_kkT[(hA*16 + k)*NN + j];
        sB += qs_s[hB*16 + k] * g_kkT[(hB*16 + k)*NN + j];
    }
    float cA = 0.f, cB = 0.f;
    #pragma unroll
    for (int k = 0; k < 12; k++) {
        cA += qp_s[hA*12 + k] * g_kpT[(hA*12 + k)*NN + j];
        cB += qp_s[hB*12 + k] * g_kpT[(hB*12 + k)*NN + j];
    }
    float dA = q2_s[hA] + g_k2[hA*NN + j] - 2.f*cA;
    float dB = q2_s[hB] + g_k2[hB*NN + j] - 2.f*cB;
    g_attn[((size_t)hA*NN + i)*NN + j] =
        SCAL_SCALE*sA - cw_s[hA]*dA + (pA + bb_s[hA])*PAIR_SCALE;
    g_attn[((size_t)hB*NN + i)*NN + j] =
        SCAL_SCALE*sB - cw_s[hB]*dB + (pB + bb_s[hB])*PAIR_SCALE;
}

// ---------------------------------------------------------------------------
// kB: softmax over j. One block per (h,i) row.
// ---------------------------------------------------------------------------
__global__ void k_softmax() {
    size_t row = blockIdx.x;
    float* p = g_attn + row * NN;
    int t = threadIdx.x; // 256
    float a = p[t], b = p[t + 256];
    __shared__ float red[256];
    red[t] = fmaxf(a, b);
    __syncthreads();
    #pragma unroll
    for (int s = 128; s > 0; s >>= 1) {
        if (t < s) red[t] = fmaxf(red[t], red[t + s]);
        __syncthreads();
    }
    float M = red[0];
    __syncthreads();
    float ea = __expf(a - M), eb = __expf(b - M);
    red[t] = ea + eb;
    __syncthreads();
    #pragma unroll
    for (int s = 128; s > 0; s >>= 1) {
        if (t < s) red[t] += red[t + s];
        __syncthreads();
    }
    float inv = 1.f / red[0];
    p[t] = ea * inv;
    p[t + 256] = eb * inv;
}

// ---------------------------------------------------------------------------
// kC: rp partials for one 64-j chunk. grid (512, 8), 256 threads.
// ---------------------------------------------------------------------------
__global__ void k_rp(const float* __restrict__ edge) {
    int i = blockIdx.x, jc = blockIdx.y, j0 = jc * 64;
    int t = threadIdx.x;
    int e4 = t & 31, jg = t >> 5;
    __shared__ float lg_s[8*64];
    __shared__ float4 red4[4*8*32];

    for (int idx = t; idx < 512; idx += 256)
        lg_s[idx] = g_attn[((size_t)(idx >> 6)*NN + i)*NN + j0 + (idx & 63)];
    __syncthreads();

    float4 acc[8];
    #pragma unroll
    for (int h = 0; h < 8; h++) acc[h] = make_float4(0.f,0.f,0.f,0.f);

    const float4* ep = (const float4*)(edge + ((size_t)i*NN + j0 + jg*8)*EE) + e4;
    #pragma unroll
    for (int jj = 0; jj < 8; jj++) {
        float4 ev = ep[(size_t)jj*32];
        #pragma unroll
        for (int h = 0; h < 8; h++) {
            float p = lg_s[h*64 + jg*8 + jj];
            acc[h].x += ev.x*p; acc[h].y += ev.y*p;
            acc[h].z += ev.z*p; acc[h].w += ev.w*p;
        }
    }
    if (jg >= 4) {
        #pragma unroll
        for (int h = 0; h < 8; h++) red4[((jg-4)*8 + h)*32 + e4] = acc[h];
    }
    __syncthreads();
    if (jg < 4) {
        #pragma unroll
        for (int h = 0; h < 8; h++) {
            float4 o = red4[(jg*8 + h)*32 + e4];
            acc[h].x += o.x; acc[h].y += o.y; acc[h].z += o.z; acc[h].w += o.w;
        }
    }
    __syncthreads();
    if (jg < 4) {
        #pragma unroll
        for (int h = 0; h < 8; h++) red4[(jg*8 + h)*32 + e4] = acc[h];
    }
    __syncthreads();
    {
        int h = t >> 5, e = t & 31;
        float4 s0 = red4[(0*8 + h)*32 + e];
        float4 s1 = red4[(1*8 + h)*32 + e];
        float4 s2 = red4[(2*8 + h)*32 + e];
        float4 s3 = red4[(3*8 + h)*32 + e];
        float4 s = make_float4(s0.x+s1.x+s2.x+s3.x, s0.y+s1.y+s2.y+s3.y,
                               s0.z+s1.z+s2.z+s3.z, s0.w+s1.w+s2.w+s3.w);
        ((float4*)(g_rpp + ((size_t)jc*NN + i)*1024))[h*32 + e] = s;
    }
}

// ---------------------------------------------------------------------------
// kD: rs / pts / norms + rp reduction -> cat. grid 512, 256 threads.
// ---------------------------------------------------------------------------
__global__ void k_assemble(const float* __restrict__ rot,
                           const float* __restrict__ trans) {
    int i = blockIdx.x, t = threadIdx.x;
    __shared__ float at_s[8*512];
    __shared__ float rs_red[2*128];
    __shared__ float pt_red[2*96];
    __shared__ float pts_s[96];

    for (int idx = t; idx < 4096; idx += 256)
        at_s[idx] = g_attn[((size_t)(idx >> 9)*NN + i)*NN + (idx & 511)];
    __syncthreads();

    float* cat = &g_cat[(size_t)i*CATD];

    // rs: 128 cols x 2 halves (all 256 threads)
    {
        int half = t >> 7, c = t & 127, h = c >> 4;
        float a = 0.f;
        #pragma unroll 8
        for (int j = 0; j < 256; j++)
            a += at_s[h*512 + half*256 + j] * g_vs[(size_t)(half*256 + j)*128 + c];
        rs_red[half*128 + c] = a;
    }
    // pts: 96 cols x 2 halves (192 threads)
    if (t < 192) {
        int half = t / 96, q = t % 96, h = q / 12;
        float a = 0.f;
        #pragma unroll 8
        for (int j = 0; j < 256; j++)
            a += at_s[h*512 + half*256 + j] * g_vp[(size_t)(half*256 + j)*96 + q];
        pt_red[half*96 + q] = a;
    }
    // rp partial sums (independent of at_s)
    for (int o = t; o < 1024; o += 256) {
        float s = 0.f;
        #pragma unroll
        for (int jc = 0; jc < 8; jc++)
            s += g_rpp[((size_t)jc*NN + i)*1024 + o];
        cat[256 + o] = s;
    }
    __syncthreads();
    if (t < 128) cat[t] = rs_red[t] + rs_red[128 + t];
    else if (t < 224) { int q = t - 128; pts_s[q] = pt_red[q] + pt_red[96 + q]; }
    __syncthreads();

    if (t < 32) {
        int base = t * 3;
        float T0 = trans[i*3], T1 = trans[i*3+1], T2 = trans[i*3+2];
        float x0 = pts_s[base] - T0, x1 = pts_s[base+1] - T1, x2 = pts_s[base+2] - T2;
        const float* R = &rot[i*9];
        float l0 = x0*R[0] + x1*R[1] + x2*R[2];
        float l1 = x0*R[3] + x1*R[4] + x2*R[5];
        float l2 = x0*R[6] + x1*R[7] + x2*R[8];
        cat[128 + base]     = l0;
        cat[128 + base + 1] = l1;
        cat[128 + base + 2] = l2;
        cat[224 + t] = sqrtf(l0*l0 + l1*l1 + l2*l2 + 1e-8f);
    }
}

// ---------------------------------------------------------------------------
// Register-blocked GEMM: 32x32 tile, BK=32, 128 threads, 2x4 micro.
// blockIdx.z selects K-slice (split-K up to 4); partial z writes to Yz.
// ---------------------------------------------------------------------------
template<int LDX, int NC, bool RELU>
__global__ void k_gemm(const float* __restrict__ X, const float* __restrict__ W,
                       const float* __restrict__ bias,
                       float* __restrict__ Y0, float* __restrict__ Y1,
                       float* __restrict__ Y2, float* __restrict__ Y3, int klen) {
    int r0 = blockIdx.x * 32, c0 = blockIdx.y * 32;
    int z = blockIdx.z;
    int kbase = z * klen;
    float* Y = (z == 0) ? Y0 : (z == 1) ? Y1 : (z == 2) ? Y2 : Y3;
    int t = threadIdx.x;
    __shared__ float Xs[32][33];
    __shared__ float Ws[32][36];

    int tx = t & 7, ty = t >> 3;
    int lrow = t >> 3, lkq = t & 7;

    float acc[2][4];
    #pragma unroll
    for (int a = 0; a < 2; a++)
        #pragma unroll
        for (int b = 0; b < 4; b++) acc[a][b] = 0.f;

    for (int kc = 0; kc < klen; kc += 32) {
        int kg = kbase + kc;
        #pragma unroll
        for (int rr = 0; rr < 2; rr++) {
            int row = lrow + rr*16;
            float4 v = *(const float4*)&X[(size_t)(r0 + row)*LDX + kg + lkq*4];
            Xs[lkq*4 + 0][row] = v.x;
            Xs[lkq*4 + 1][row] = v.y;
            Xs[lkq*4 + 2][row] = v.z;
            Xs[lkq*4 + 3][row] = v.w;
        }
        #pragma unroll
        for (int rr = 0; rr < 2; rr++) {
            int k = lrow + rr*16;
            float4 v = *(const float4*)&W[(size_t)(kg + k)*NC + c0 + lkq*4];
            *(float4*)&Ws[k][lkq*4] = v;
        }
        __syncthreads();

        #pragma unroll
        for (int k = 0; k < 32; k++) {
            float x0 = Xs[k][ty*2 + 0];
            float x1 = Xs[k][ty*2 + 1];
            float4 wv = *(const float4*)&Ws[k][tx*4];
            acc[0][0] += x0*wv.x; acc[0][1] += x0*wv.y;
            acc[0][2] += x0*wv.z; acc[0][3] += x0*wv.w;
            acc[1][0] += x1*wv.x; acc[1][1] += x1*wv.y;
            acc[1][2] += x1*wv.z; acc[1][3] += x1*wv.w;
        }
        __syncthreads();
    }

    #pragma unroll
    for (int a = 0; a < 2; a++) {
        int row = r0 + ty*2 + a;
        #pragma unroll
        for (int b = 0; b < 4; b++) {
            int col = c0 + tx*4 + b;
            float v = acc[a][b];
            if (z == 0) v += bias[col];
            if (RELU) v = fmaxf(v, 0.f);
            Y[(size_t)row*NC + col] = v;
        }
    }
}

// ---------------------------------------------------------------------------
// LayerNorm over 384 of (a+b+c+d). 128 threads, 3 elems each.
// ---------------------------------------------------------------------------
__global__ void k_ln4(const float* __restrict__ ia, const float* __restrict__ ib,
                      const float* __restrict__ ic, const float* __restrict__ id,
                      const float* __restrict__ g, const float* __restrict__ b,
                      float* __restrict__ out) {
    int i = blockIdx.x, t = threadIdx.x;
    __shared__ float red[128];
    float v0 = ia[i*DD+t]     + ib[i*DD+t]     + ic[i*DD+t]     + id[i*DD+t];
    float v1 = ia[i*DD+t+128] + ib[i*DD+t+128] + ic[i*DD+t+128] + id[i*DD+t+128];
    float v2 = ia[i*DD+t+256] + ib[i*DD+t+256] + ic[i*DD+t+256] + id[i*DD+t+256];
    red[t] = v0 + v1 + v2;
    __syncthreads();
    #pragma unroll
    for (int s = 64; s > 0; s >>= 1) { if (t < s) red[t] += red[t+s]; __syncthreads(); }
    float mu = red[0] * (1.f/384.f);
    __syncthreads();
    float d0 = v0-mu, d1 = v1-mu, d2 = v2-mu;
    red[t] = d0*d0 + d1*d1 + d2*d2;
    __syncthreads();
    #pragma unroll
    for (int s = 64; s > 0; s >>= 1) { if (t < s) red[t] += red[t+s]; __syncthreads(); }
    float inv = rsqrtf(red[0] * (1.f/384.f) + 1e-5f);
    out[i*DD + t]       = d0*inv*g[t]       + b[t];
    out[i*DD + t + 128] = d1*inv*g[t+128]   + b[t+128];
    out[i*DD + t + 256] = d2*inv*g[t+256]   + b[t+256];
}

// ---------------------------------------------------------------------------
extern "C" void kernel_launch(void* const* d_in, const int* in_sizes, int n_in,
                              void* d_out, int out_size) {
    const float* node  = (const float*)d_in[0];
    const float* edge  = (const float*)d_in[1];
    const float* rot   = (const float*)d_in[2];
    const float* trans = (const float*)d_in[3];
    const float* Wq_s = (const float*)d_in[5];
    const float* Wk_s = (const float*)d_in[6];
    const float* Wv_s = (const float*)d_in[7];
    const float* Wq_p = (const float*)d_in[8];
    const float* Wk_p = (const float*)d_in[9];
    const float* Wv_p = (const float*)d_in[10];
    const float* pw   = (const float*)d_in[11];
    const float* Wb   = (const float*)d_in[12];
    const float* bb   = (const float*)d_in[13];
    const float* Wo   = (const float*)d_in[14];
    const float* bo   = (const float*)d_in[15];
    const float* g1   = (const float*)d_in[16];
    const float* beta1= (const float*)d_in[17];
    const float* W1   = (const float*)d_in[18];
    const float* b1   = (const float*)d_in[19];
    const float* W2   = (const float*)d_in[20];
    const float* b2   = (const float*)d_in[21];
    const float* W3   = (const float*)d_in[22];
    const float* b3   = (const float*)d_in[23];
    const float* g2   = (const float*)d_in[24];
    const float* beta2= (const float*)d_in[25];
    float* out = (float*)d_out;

    float *p_cat, *p_t0, *p_t1, *p_t2, *p_t3, *p_x1, *p_h1, *p_h2;
    float *p_Wall, *p_zero, *p_proj;
    cudaGetSymbolAddress((void**)&p_cat, g_cat);
    cudaGetSymbolAddress((void**)&p_t0, g_t0);
    cudaGetSymbolAddress((void**)&p_t1, g_t1);
    cudaGetSymbolAddress((void**)&p_t2, g_t2);
    cudaGetSymbolAddress((void**)&p_t3, g_t3);
    cudaGetSymbolAddress((void**)&p_x1, g_x1);
    cudaGetSymbolAddress((void**)&p_h1, g_h1);
    cudaGetSymbolAddress((void**)&p_h2, g_h2);
    cudaGetSymbolAddress((void**)&p_Wall, g_Wall);
    cudaGetSymbolAddress((void**)&p_zero, g_zero);
    cudaGetSymbolAddress((void**)&p_proj, g_proj);

    // 1: pack weights (+zero bias)
    k_packW<<<(DD*PCOLS + 255)/256, 256>>>(Wq_s, Wk_s, Wv_s, Wq_p, Wk_p, Wv_p);
    // 2: projection GEMM 512x672x384
    k_gemm<DD, PCOLS, false><<<dim3(16, 21, 1), 128>>>(node, p_Wall, p_zero,
                                                        p_proj, p_proj, p_proj, p_proj, DD);
    // 3: scatter + rigid + norms
    k_post<<<NN, 128>>>(rot, trans);
    // 4: logits  <-- profiled slot
    k_logits<<<dim3(NN, 8), 256>>>(edge, Wb, bb, pw);
    // 5: softmax
    k_softmax<<<HH*NN, 256>>>();
    // 6: rp partials
    k_rp<<<dim3(NN, 8), 256>>>(edge);
    // 7: assemble cat
    k_assemble<<<NN, 256>>>(rot, trans);

    // Wo: split-K 4 x 320
    k_gemm<CATD, DD, false><<<dim3(16, 12, 4), 128>>>(p_cat, Wo, bo, p_t0, p_t1, p_t2, p_t3, 320);
    k_ln4<<<NN, 128>>>(p_t0, p_t1, p_t2, p_t3, g1, beta1, p_x1);
    // MLP
    k_gemm<DD, HID, true><<<dim3(16, 24, 1), 128>>>(p_x1, W1, b1, p_h1, p_h1, p_h1, p_h1, 384);
    k_gemm<HID, HID, true><<<dim3(16, 24, 1), 128>>>(p_h1, W2, b2, p_h2, p_h2, p_h2, p_h2, 768);
    // W3: split-K 4 x 192
    k_gemm<HID, DD, false><<<dim3(16, 12, 4), 128>>>(p_h2, W3, b3, p_t0, p_t1, p_t2, p_t3, 192);
    k_ln4<<<NN, 128>>>(p_t0, p_t1, p_t2, p_t3, g2, beta2, out);
}

// round 7
// speedup vs baseline: 2.8059x; 1.1789x over previous
#include <cuda_runtime.h>
#include <cuda_bf16.h>
#include <math.h>

#define NN 512
#define DD 384
#define EE 128
#define HH 8
#define CATD 1280
#define HID 768
#define PCOLS 672

static __device__ __constant__ float SCAL_SCALE = 0.14433756729740643f; // (3*16)^-0.5
static __device__ __constant__ float POINT_SCALE = 0.13608276348795434f; // (3*4*4.5)^-0.5
static __device__ __constant__ float PAIR_SCALE = 0.5773502691896258f;  // 3^-0.5

// scratch
__device__ float g_Wall[DD*PCOLS];
__device__ float g_zero[PCOLS];
__device__ float g_proj[NN*PCOLS];
__device__ float g_qs[NN*128];
__device__ float g_kkT[128*NN];   // [h*16+k][j]
__device__ float g_vs[NN*128];
__device__ float g_qp[NN*96];
__device__ float g_kpT[96*NN];    // [h*12+q][j]
__device__ float g_vp[NN*96];
__device__ float g_q2[HH*NN];
__device__ float g_k2[HH*NN];
__device__ float g_attn[(size_t)HH*NN*NN];
__device__ float g_rpp[(size_t)8*NN*1024];   // rp partials [jc][i][h*128+e]
__device__ float g_cat[(size_t)NN*CATD];
__device__ float g_t0[NN*DD];
__device__ float g_t1[NN*DD];
__device__ float g_t2[NN*DD];
__device__ float g_t3[NN*DD];
__device__ float g_x1[NN*DD];
__device__ float g_h1[NN*HID];
__device__ float g_h2[NN*HID];

// ---------------------------------------------------------------------------
// K0: pack projection weights into one [384 x 672] matrix + zero bias
// ---------------------------------------------------------------------------
__global__ void k_packW(const float* __restrict__ Wq_s, const float* __restrict__ Wk_s,
                        const float* __restrict__ Wv_s,
                        const float* __restrict__ Wq_p, const float* __restrict__ Wk_p,
                        const float* __restrict__ Wv_p) {
    int idx = blockIdx.x * 256 + threadIdx.x;
    if (idx < PCOLS) g_zero[idx] = 0.f;
    if (idx >= DD*PCOLS) return;
    int r = idx / PCOLS, c = idx % PCOLS;
    float v;
    if (c < 128)      v = Wq_s[r*128 + c];
    else if (c < 256) v = Wk_s[r*128 + (c-128)];
    else if (c < 384) v = Wv_s[r*128 + (c-256)];
    else if (c < 480) v = Wq_p[r*96 + (c-384)];
    else if (c < 576) v = Wk_p[r*96 + (c-480)];
    else              v = Wv_p[r*96 + (c-576)];
    g_Wall[idx] = v;
}

// ---------------------------------------------------------------------------
// K_post: scatter proj results, rigid transforms, q2/k2. One block per i.
// ---------------------------------------------------------------------------
__global__ void k_post(const float* __restrict__ rot,
                       const float* __restrict__ trans) {
    int i = blockIdx.x, t = threadIdx.x; // 128
    __shared__ float pg[192];
    const float* pr = &g_proj[i*PCOLS];

    float a = pr[t];
    g_qs[i*128 + t] = a;
    g_kkT[t*NN + i] = pr[128 + t];
    g_vs[i*128 + t] = pr[256 + t];

    const float* R = &rot[i*9];
    float T[3] = {trans[i*3], trans[i*3+1], trans[i*3+2]};
    for (int q = t; q < 288; q += 128) {
        int m = q / 96, qq = q % 96;
        int hd = qq / 3, rr = qq % 3;
        float v = T[rr];
        #pragma unroll
        for (int c = 0; c < 3; c++) v += pr[384 + m*96 + hd*3 + c] * R[c*3 + rr];
        if (m == 0)      { g_qp[i*96 + qq] = v; pg[qq] = v; }
        else if (m == 1) { g_kpT[qq*NN + i] = v; pg[96 + qq] = v; }
        else               g_vp[i*96 + qq] = v;
    }
    __syncthreads();

    if (t < 16) {
        int m = t >> 3, h = t & 7;
        float s = 0.f;
        #pragma unroll
        for (int q = 0; q < 12; q++) { float v = pg[m*96 + h*12 + q]; s += v*v; }
        (m ? g_k2 : g_q2)[h*NN + i] = s;
    }
}

// ---------------------------------------------------------------------------
// kA: logits for one 64-j chunk. grid (512, 8), 256 threads.
// Quarter-split pair-bias: each edge row pulled through LDS once.
// ---------------------------------------------------------------------------
__global__ void k_logits(const float* __restrict__ edge,
                         const float* __restrict__ Wb,
                         const float* __restrict__ bb,
                         const float* __restrict__ pw) {
    int i = blockIdx.x, jc = blockIdx.y, j0 = jc * 64;
    int t = threadIdx.x; // 256
    __shared__ float qs_s[128], qp_s[96], q2_s[8], cw_s[8], bb_s[8];
    __shared__ float4 wb4[32*8];
    __shared__ float4 edge_s[64*33];
    __shared__ float pair_red[4][64][9];

    if (t < 128) qs_s[t] = g_qs[i*128 + t];
    else if (t < 224) qp_s[t-128] = g_qp[i*96 + (t-128)];
    else if (t < 232) {
        int h = t - 224;
        q2_s[h] = g_q2[h*NN + i];
        bb_s[h] = bb[h];
        cw_s[h] = 0.5f * POINT_SCALE * log1pf(__expf(pw[h]));
    }
    {
        int eg = t >> 3, h = t & 7;
        wb4[eg*8 + h] = make_float4(Wb[(eg*4+0)*8 + h], Wb[(eg*4+1)*8 + h],
                                    Wb[(eg*4+2)*8 + h], Wb[(eg*4+3)*8 + h]);
    }
    {
        const float4* eg = (const float4*)(edge + ((size_t)i*NN + j0)*EE);
        #pragma unroll 8
        for (int idx = t; idx < 2048; idx += 256)
            edge_s[(idx >> 5)*33 + (idx & 31)] = eg[idx];
    }
    __syncthreads();

    int jl = t & 63, q = t >> 6;
    // phase 1: each thread reduces 8 f4-groups into 8 head partials
    {
        float p[8] = {0.f,0.f,0.f,0.f,0.f,0.f,0.f,0.f};
        #pragma unroll
        for (int gg = 0; gg < 8; gg++) {
            int g = q*8 + gg;
            float4 ev = edge_s[jl*33 + g];
            #pragma unroll
            for (int h = 0; h < 8; h++) {
                float4 w = wb4[g*8 + h];
                p[h] += ev.x*w.x + ev.y*w.y + ev.z*w.z + ev.w*w.w;
            }
        }
        #pragma unroll
        for (int h = 0; h < 8; h++) pair_red[q][jl][h] = p[h];
    }
    __syncthreads();

    // phase 2: thread owns (j, hA) and (j, hB)
    int hA = q, hB = q + 4;
    float pA = pair_red[0][jl][hA] + pair_red[1][jl][hA]
             + pair_red[2][jl][hA] + pair_red[3][jl][hA];
    float pB = pair_red[0][jl][hB] + pair_red[1][jl][hB]
             + pair_red[2][jl][hB] + pair_red[3][jl][hB];
    int j = j0 + jl;
    float sA = 0.f, sB = 0.f;
    #pragma unroll
    for (int k = 0; k < 16; k++) {
        sA += qs_s[hA*16 + k] * g_kkT[(hA*16 + k)*NN + j];
        sB += qs_s[hB*16 + k] * g_kkT[(hB*16 + k)*NN + j];
    }
    float cA = 0.f, cB = 0.f;
    #pragma unroll
    for (int k = 0; k < 12; k++) {
        cA += qp_s[hA*12 + k] * g_kpT[(hA*12 + k)*NN + j];
        cB += qp_s[hB*12 + k] * g_kpT[(hB*12 + k)*NN + j];
    }
    float dA = q2_s[hA] + g_k2[hA*NN + j] - 2.f*cA;
    float dB = q2_s[hB] + g_k2[hB*NN + j] - 2.f*cB;
    g_attn[((size_t)hA*NN + i)*NN + j] =
        SCAL_SCALE*sA - cw_s[hA]*dA + (pA + bb_s[hA])*PAIR_SCALE;
    g_attn[((size_t)hB*NN + i)*NN + j] =
        SCAL_SCALE*sB - cw_s[hB]*dB + (pB + bb_s[hB])*PAIR_SCALE;
}

// ---------------------------------------------------------------------------
// kB: softmax over j. One block per (h,i) row.
// ---------------------------------------------------------------------------
__global__ void k_softmax() {
    size_t row = blockIdx.x;
    float* p = g_attn + row * NN;
    int t = threadIdx.x; // 256
    float a = p[t], b = p[t + 256];
    __shared__ float red[256];
    red[t] = fmaxf(a, b);
    __syncthreads();
    #pragma unroll
    for (int s = 128; s > 0; s >>= 1) {
        if (t < s) red[t] = fmaxf(red[t], red[t + s]);
        __syncthreads();
    }
    float M = red[0];
    __syncthreads();
    float ea = __expf(a - M), eb = __expf(b - M);
    red[t] = ea + eb;
    __syncthreads();
    #pragma unroll
    for (int s = 128; s > 0; s >>= 1) {
        if (t < s) red[t] += red[t + s];
        __syncthreads();
    }
    float inv = 1.f / red[0];
    p[t] = ea * inv;
    p[t + 256] = eb * inv;
}

// ---------------------------------------------------------------------------
// kC: rp partials for one 64-j chunk. grid (512, 8), 256 threads.
// ---------------------------------------------------------------------------
__global__ void k_rp(const float* __restrict__ edge) {
    int i = blockIdx.x, jc = blockIdx.y, j0 = jc * 64;
    int t = threadIdx.x;
    int e4 = t & 31, jg = t >> 5;
    __shared__ float lg_s[8*64];
    __shared__ float4 red4[4*8*32];

    for (int idx = t; idx < 512; idx += 256)
        lg_s[idx] = g_attn[((size_t)(idx >> 6)*NN + i)*NN + j0 + (idx & 63)];
    __syncthreads();

    float4 acc[8];
    #pragma unroll
    for (int h = 0; h < 8; h++) acc[h] = make_float4(0.f,0.f,0.f,0.f);

    const float4* ep = (const float4*)(edge + ((size_t)i*NN + j0 + jg*8)*EE) + e4;
    #pragma unroll
    for (int jj = 0; jj < 8; jj++) {
        float4 ev = ep[(size_t)jj*32];
        #pragma unroll
        for (int h = 0; h < 8; h++) {
            float p = lg_s[h*64 + jg*8 + jj];
            acc[h].x += ev.x*p; acc[h].y += ev.y*p;
            acc[h].z += ev.z*p; acc[h].w += ev.w*p;
        }
    }
    if (jg >= 4) {
        #pragma unroll
        for (int h = 0; h < 8; h++) red4[((jg-4)*8 + h)*32 + e4] = acc[h];
    }
    __syncthreads();
    if (jg < 4) {
        #pragma unroll
        for (int h = 0; h < 8; h++) {
            float4 o = red4[(jg*8 + h)*32 + e4];
            acc[h].x += o.x; acc[h].y += o.y; acc[h].z += o.z; acc[h].w += o.w;
        }
    }
    __syncthreads();
    if (jg < 4) {
        #pragma unroll
        for (int h = 0; h < 8; h++) red4[(jg*8 + h)*32 + e4] = acc[h];
    }
    __syncthreads();
    {
        int h = t >> 5, e = t & 31;
        float4 s0 = red4[(0*8 + h)*32 + e];
        float4 s1 = red4[(1*8 + h)*32 + e];
        float4 s2 = red4[(2*8 + h)*32 + e];
        float4 s3 = red4[(3*8 + h)*32 + e];
        float4 s = make_float4(s0.x+s1.x+s2.x+s3.x, s0.y+s1.y+s2.y+s3.y,
                               s0.z+s1.z+s2.z+s3.z, s0.w+s1.w+s2.w+s3.w);
        ((float4*)(g_rpp + ((size_t)jc*NN + i)*1024))[h*32 + e] = s;
    }
}

// ---------------------------------------------------------------------------
// kD: rs / pts / norms + rp reduction -> cat. grid 512, 256 threads.
// ---------------------------------------------------------------------------
__global__ void k_assemble(const float* __restrict__ rot,
                           const float* __restrict__ trans) {
    int i = blockIdx.x, t = threadIdx.x;
    __shared__ float at_s[8*512];
    __shared__ float rs_red[2*128];
    __shared__ float pt_red[2*96];
    __shared__ float pts_s[96];

    for (int idx = t; idx < 4096; idx += 256)
        at_s[idx] = g_attn[((size_t)(idx >> 9)*NN + i)*NN + (idx & 511)];
    __syncthreads();

    float* cat = &g_cat[(size_t)i*CATD];

    {
        int half = t >> 7, c = t & 127, h = c >> 4;
        float a = 0.f;
        #pragma unroll 8
        for (int j = 0; j < 256; j++)
            a += at_s[h*512 + half*256 + j] * g_vs[(size_t)(half*256 + j)*128 + c];
        rs_red[half*128 + c] = a;
    }
    if (t < 192) {
        int half = t / 96, q = t % 96, h = q / 12;
        float a = 0.f;
        #pragma unroll 8
        for (int j = 0; j < 256; j++)
            a += at_s[h*512 + half*256 + j] * g_vp[(size_t)(half*256 + j)*96 + q];
        pt_red[half*96 + q] = a;
    }
    for (int o = t; o < 1024; o += 256) {
        float s = 0.f;
        #pragma unroll
        for (int jc = 0; jc < 8; jc++)
            s += g_rpp[((size_t)jc*NN + i)*1024 + o];
        cat[256 + o] = s;
    }
    __syncthreads();
    if (t < 128) cat[t] = rs_red[t] + rs_red[128 + t];
    else if (t < 224) { int q = t - 128; pts_s[q] = pt_red[q] + pt_red[96 + q]; }
    __syncthreads();

    if (t < 32) {
        int base = t * 3;
        float T0 = trans[i*3], T1 = trans[i*3+1], T2 = trans[i*3+2];
        float x0 = pts_s[base] - T0, x1 = pts_s[base+1] - T1, x2 = pts_s[base+2] - T2;
        const float* R = &rot[i*9];
        float l0 = x0*R[0] + x1*R[1] + x2*R[2];
        float l1 = x0*R[3] + x1*R[4] + x2*R[5];
        float l2 = x0*R[6] + x1*R[7] + x2*R[8];
        cat[128 + base]     = l0;
        cat[128 + base + 1] = l1;
        cat[128 + base + 2] = l2;
        cat[224 + t] = sqrtf(l0*l0 + l1*l1 + l2*l2 + 1e-8f);
    }
}

// ---------------------------------------------------------------------------
// GEMM A (proj only): 32x32 tile, BK=32, 128 threads, 2x4 micro.
// ---------------------------------------------------------------------------
template<int LDX, int NC>
__global__ void k_gemm32(const float* __restrict__ X, const float* __restrict__ W,
                         const float* __restrict__ bias, float* __restrict__ Y, int klen) {
    int r0 = blockIdx.x * 32, c0 = blockIdx.y * 32;
    int t = threadIdx.x;
    __shared__ float Xs[32][33];
    __shared__ float Ws[32][36];

    int tx = t & 7, ty = t >> 3;
    int lrow = t >> 3, lkq = t & 7;

    float acc[2][4];
    #pragma unroll
    for (int a = 0; a < 2; a++)
        #pragma unroll
        for (int b = 0; b < 4; b++) acc[a][b] = 0.f;

    for (int kg = 0; kg < klen; kg += 32) {
        #pragma unroll
        for (int rr = 0; rr < 2; rr++) {
            int row = lrow + rr*16;
            float4 v = *(const float4*)&X[(size_t)(r0 + row)*LDX + kg + lkq*4];
            Xs[lkq*4 + 0][row] = v.x;
            Xs[lkq*4 + 1][row] = v.y;
            Xs[lkq*4 + 2][row] = v.z;
            Xs[lkq*4 + 3][row] = v.w;
        }
        #pragma unroll
        for (int rr = 0; rr < 2; rr++) {
            int k = lrow + rr*16;
            float4 v = *(const float4*)&W[(size_t)(kg + k)*NC + c0 + lkq*4];
            *(float4*)&Ws[k][lkq*4] = v;
        }
        __syncthreads();

        #pragma unroll
        for (int k = 0; k < 32; k++) {
            float x0 = Xs[k][ty*2 + 0];
            float x1 = Xs[k][ty*2 + 1];
            float4 wv = *(const float4*)&Ws[k][tx*4];
            acc[0][0] += x0*wv.x; acc[0][1] += x0*wv.y;
            acc[0][2] += x0*wv.z; acc[0][3] += x0*wv.w;
            acc[1][0] += x1*wv.x; acc[1][1] += x1*wv.y;
            acc[1][2] += x1*wv.z; acc[1][3] += x1*wv.w;
        }
        __syncthreads();
    }

    #pragma unroll
    for (int a = 0; a < 2; a++) {
        int row = r0 + ty*2 + a;
        #pragma unroll
        for (int b = 0; b < 4; b++) {
            int col = c0 + tx*4 + b;
            Y[(size_t)row*NC + col] = acc[a][b] + bias[col];
        }
    }
}

// ---------------------------------------------------------------------------
// GEMM B: 32x64 tile, BK=32, 128 threads, 4x4 micro. Split-K via blockIdx.z.
// ---------------------------------------------------------------------------
template<int LDX, int NC, bool RELU>
__global__ void k_gemm64(const float* __restrict__ X, const float* __restrict__ W,
                         const float* __restrict__ bias,
                         float* __restrict__ Y0, float* __restrict__ Y1,
                         float* __restrict__ Y2, float* __restrict__ Y3, int klen) {
    int r0 = blockIdx.x * 32, c0 = blockIdx.y * 64;
    int z = blockIdx.z;
    int kbase = z * klen;
    float* Y = (z == 0) ? Y0 : (z == 1) ? Y1 : (z == 2) ? Y2 : Y3;
    int t = threadIdx.x;
    __shared__ float Xs[32][36];   // [k][m], 36 pad -> 16B-aligned rows
    __shared__ float Ws[32][68];   // [k][n], 68 pad -> 16B-aligned rows

    int tx = t & 15, ty = t >> 4;  // compute: rows ty*4.., cols tx*4..

    float acc[4][4];
    #pragma unroll
    for (int a = 0; a < 4; a++)
        #pragma unroll
        for (int b = 0; b < 4; b++) acc[a][b] = 0.f;

    int xrow = t >> 2, xk4 = t & 3;   // X loads: 2 f4 per thread
    for (int kc = 0; kc < klen; kc += 32) {
        int kg = kbase + kc;
        #pragma unroll
        for (int hh = 0; hh < 2; hh++) {
            int kq = xk4*2 + hh;  // f4 index 0..7
            float4 v = *(const float4*)&X[(size_t)(r0 + xrow)*LDX + kg + kq*4];
            Xs[kq*4 + 0][xrow] = v.x;
            Xs[kq*4 + 1][xrow] = v.y;
            Xs[kq*4 + 2][xrow] = v.z;
            Xs[kq*4 + 3][xrow] = v.w;
        }
        #pragma unroll
        for (int it = 0; it < 4; it++) {
            int idx = t + 128*it;           // 0..511
            int k = idx >> 4, cf4 = idx & 15;
            float4 v = *(const float4*)&W[(size_t)(kg + k)*NC + c0 + cf4*4];
            *(float4*)&Ws[k][cf4*4] = v;
        }
        __syncthreads();

        #pragma unroll
        for (int k = 0; k < 32; k++) {
            float4 xv = *(const float4*)&Xs[k][ty*4];
            float4 wv = *(const float4*)&Ws[k][tx*4];
            acc[0][0] += xv.x*wv.x; acc[0][1] += xv.x*wv.y; acc[0][2] += xv.x*wv.z; acc[0][3] += xv.x*wv.w;
            acc[1][0] += xv.y*wv.x; acc[1][1] += xv.y*wv.y; acc[1][2] += xv.y*wv.z; acc[1][3] += xv.y*wv.w;
            acc[2][0] += xv.z*wv.x; acc[2][1] += xv.z*wv.y; acc[2][2] += xv.z*wv.z; acc[2][3] += xv.z*wv.w;
            acc[3][0] += xv.w*wv.x; acc[3][1] += xv.w*wv.y; acc[3][2] += xv.w*wv.z; acc[3][3] += xv.w*wv.w;
        }
        __syncthreads();
    }

    #pragma unroll
    for (int a = 0; a < 4; a++) {
        int row = r0 + ty*4 + a;
        #pragma unroll
        for (int b = 0; b < 4; b++) {
            int col = c0 + tx*4 + b;
            float v = acc[a][b];
            if (z == 0) v += bias[col];
            if (RELU) v = fmaxf(v, 0.f);
            Y[(size_t)row*NC + col] = v;
        }
    }
}

// ---------------------------------------------------------------------------
// LayerNorm over 384 of (a+b+c+d). 128 threads, 3 elems each.
// ---------------------------------------------------------------------------
__global__ void k_ln4(const float* __restrict__ ia, const float* __restrict__ ib,
                      const float* __restrict__ ic, const float* __restrict__ id,
                      const float* __restrict__ g, const float* __restrict__ b,
                      float* __restrict__ out) {
    int i = blockIdx.x, t = threadIdx.x;
    __shared__ float red[128];
    float v0 = ia[i*DD+t]     + ib[i*DD+t]     + ic[i*DD+t]     + id[i*DD+t];
    float v1 = ia[i*DD+t+128] + ib[i*DD+t+128] + ic[i*DD+t+128] + id[i*DD+t+128];
    float v2 = ia[i*DD+t+256] + ib[i*DD+t+256] + ic[i*DD+t+256] + id[i*DD+t+256];
    red[t] = v0 + v1 + v2;
    __syncthreads();
    #pragma unroll
    for (int s = 64; s > 0; s >>= 1) { if (t < s) red[t] += red[t+s]; __syncthreads(); }
    float mu = red[0] * (1.f/384.f);
    __syncthreads();
    float d0 = v0-mu, d1 = v1-mu, d2 = v2-mu;
    red[t] = d0*d0 + d1*d1 + d2*d2;
    __syncthreads();
    #pragma unroll
    for (int s = 64; s > 0; s >>= 1) { if (t < s) red[t] += red[t+s]; __syncthreads(); }
    float inv = rsqrtf(red[0] * (1.f/384.f) + 1e-5f);
    out[i*DD + t]       = d0*inv*g[t]       + b[t];
    out[i*DD + t + 128] = d1*inv*g[t+128]   + b[t+128];
    out[i*DD + t + 256] = d2*inv*g[t+256]   + b[t+256];
}

// ---------------------------------------------------------------------------
extern "C" void kernel_launch(void* const* d_in, const int* in_sizes, int n_in,
                              void* d_out, int out_size) {
    const float* node  = (const float*)d_in[0];
    const float* edge  = (const float*)d_in[1];
    const float* rot   = (const float*)d_in[2];
    const float* trans = (const float*)d_in[3];
    const float* Wq_s = (const float*)d_in[5];
    const float* Wk_s = (const float*)d_in[6];
    const float* Wv_s = (const float*)d_in[7];
    const float* Wq_p = (const float*)d_in[8];
    const float* Wk_p = (const float*)d_in[9];
    const float* Wv_p = (const float*)d_in[10];
    const float* pw   = (const float*)d_in[11];
    const float* Wb   = (const float*)d_in[12];
    const float* bb   = (const float*)d_in[13];
    const float* Wo   = (const float*)d_in[14];
    const float* bo   = (const float*)d_in[15];
    const float* g1   = (const float*)d_in[16];
    const float* beta1= (const float*)d_in[17];
    const float* W1   = (const float*)d_in[18];
    const float* b1   = (const float*)d_in[19];
    const float* W2   = (const float*)d_in[20];
    const float* b2   = (const float*)d_in[21];
    const float* W3   = (const float*)d_in[22];
    const float* b3   = (const float*)d_in[23];
    const float* g2   = (const float*)d_in[24];
    const float* beta2= (const float*)d_in[25];
    float* out = (float*)d_out;

    float *p_cat, *p_t0, *p_t1, *p_t2, *p_t3, *p_x1, *p_h1, *p_h2;
    float *p_Wall, *p_zero, *p_proj;
    cudaGetSymbolAddress((void**)&p_cat, g_cat);
    cudaGetSymbolAddress((void**)&p_t0, g_t0);
    cudaGetSymbolAddress((void**)&p_t1, g_t1);
    cudaGetSymbolAddress((void**)&p_t2, g_t2);
    cudaGetSymbolAddress((void**)&p_t3, g_t3);
    cudaGetSymbolAddress((void**)&p_x1, g_x1);
    cudaGetSymbolAddress((void**)&p_h1, g_h1);
    cudaGetSymbolAddress((void**)&p_h2, g_h2);
    cudaGetSymbolAddress((void**)&p_Wall, g_Wall);
    cudaGetSymbolAddress((void**)&p_zero, g_zero);
    cudaGetSymbolAddress((void**)&p_proj, g_proj);

    k_packW<<<(DD*PCOLS + 255)/256, 256>>>(Wq_s, Wk_s, Wv_s, Wq_p, Wk_p, Wv_p);
    k_gemm32<DD, PCOLS><<<dim3(16, 21), 128>>>(node, p_Wall, p_zero, p_proj, DD);
    k_post<<<NN, 128>>>(rot, trans);
    k_logits<<<dim3(NN, 8), 256>>>(edge, Wb, bb, pw);
    k_softmax<<<HH*NN, 256>>>();
    k_rp<<<dim3(NN, 8), 256>>>(edge);
    k_assemble<<<NN, 256>>>(rot, trans);

    // Wo: split-K 4 x 320
    k_gemm64<CATD, DD, false><<<dim3(16, 6, 4), 128>>>(p_cat, Wo, bo, p_t0, p_t1, p_t2, p_t3, 320);
    k_ln4<<<NN, 128>>>(p_t0, p_t1, p_t2, p_t3, g1, beta1, p_x1);
    // MLP
    k_gemm64<DD, HID, true><<<dim3(16, 12, 1), 128>>>(p_x1, W1, b1, p_h1, p_h1, p_h1, p_h1, 384);
    k_gemm64<HID, HID, true><<<dim3(16, 12, 1), 128>>>(p_h1, W2, b2, p_h2, p_h2, p_h2, p_h2, 768);
    // W3: split-K 4 x 192
    k_gemm64<HID, DD, false><<<dim3(16, 6, 4), 128>>>(p_h2, W3, b3, p_t0, p_t1, p_t2, p_t3, 192);
    k_ln4<<<NN, 128>>>(p_t0, p_t1, p_t2, p_t3, g2, beta2, out);
}

// round 8
// speedup vs baseline: 2.8098x; 1.0014x over previous
#include <cuda_runtime.h>
#include <cuda_bf16.h>
#include <math.h>

#define NN 512
#define DD 384
#define EE 128
#define HH 8
#define CATD 1280
#define HID 768
#define PCOLS 672

static __device__ __constant__ float SCAL_SCALE = 0.14433756729740643f; // (3*16)^-0.5
static __device__ __constant__ float POINT_SCALE = 0.13608276348795434f; // (3*4*4.5)^-0.5
static __device__ __constant__ float PAIR_SCALE = 0.5773502691896258f;  // 3^-0.5

// scratch
__device__ float g_Wall[DD*PCOLS];
__device__ float g_zero[PCOLS];
__device__ float g_proj[NN*PCOLS];
__device__ float g_qs[NN*128];
__device__ float g_kkT[128*NN];   // [h*16+k][j]
__device__ float g_vs[NN*128];
__device__ float g_qp[NN*96];
__device__ float g_kpT[96*NN];    // [h*12+q][j]
__device__ float g_vp[NN*96];
__device__ float g_q2[HH*NN];
__device__ float g_k2[HH*NN];
__device__ float g_attn[(size_t)HH*NN*NN];
__device__ float g_rpp[(size_t)8*NN*1024];   // rp partials [jc][i][h*128+e]
__device__ float g_cat[(size_t)NN*CATD];
__device__ float g_t0[NN*DD];
__device__ float g_t1[NN*DD];
__device__ float g_t2[NN*DD];
__device__ float g_t3[NN*DD];
__device__ float g_x1[NN*DD];
__device__ float g_h1[NN*HID];
__device__ float g_h2[NN*HID];

// ---------------------------------------------------------------------------
// K0: pack projection weights into one [384 x 672] matrix + zero bias
// ---------------------------------------------------------------------------
__global__ void k_packW(const float* __restrict__ Wq_s, const float* __restrict__ Wk_s,
                        const float* __restrict__ Wv_s,
                        const float* __restrict__ Wq_p, const float* __restrict__ Wk_p,
                        const float* __restrict__ Wv_p) {
    int idx = blockIdx.x * 256 + threadIdx.x;
    if (idx < PCOLS) g_zero[idx] = 0.f;
    if (idx >= DD*PCOLS) return;
    int r = idx / PCOLS, c = idx % PCOLS;
    float v;
    if (c < 128)      v = Wq_s[r*128 + c];
    else if (c < 256) v = Wk_s[r*128 + (c-128)];
    else if (c < 384) v = Wv_s[r*128 + (c-256)];
    else if (c < 480) v = Wq_p[r*96 + (c-384)];
    else if (c < 576) v = Wk_p[r*96 + (c-480)];
    else              v = Wv_p[r*96 + (c-576)];
    g_Wall[idx] = v;
}

// ---------------------------------------------------------------------------
// K_post: scatter proj results, rigid transforms, q2/k2. One block per i.
// ---------------------------------------------------------------------------
__global__ void k_post(const float* __restrict__ rot,
                       const float* __restrict__ trans) {
    int i = blockIdx.x, t = threadIdx.x; // 128
    __shared__ float pg[192];
    const float* pr = &g_proj[i*PCOLS];

    float a = pr[t];
    g_qs[i*128 + t] = a;
    g_kkT[t*NN + i] = pr[128 + t];
    g_vs[i*128 + t] = pr[256 + t];

    const float* R = &rot[i*9];
    float T[3] = {trans[i*3], trans[i*3+1], trans[i*3+2]};
    for (int q = t; q < 288; q += 128) {
        int m = q / 96, qq = q % 96;
        int hd = qq / 3, rr = qq % 3;
        float v = T[rr];
        #pragma unroll
        for (int c = 0; c < 3; c++) v += pr[384 + m*96 + hd*3 + c] * R[c*3 + rr];
        if (m == 0)      { g_qp[i*96 + qq] = v; pg[qq] = v; }
        else if (m == 1) { g_kpT[qq*NN + i] = v; pg[96 + qq] = v; }
        else               g_vp[i*96 + qq] = v;
    }
    __syncthreads();

    if (t < 16) {
        int m = t >> 3, h = t & 7;
        float s = 0.f;
        #pragma unroll
        for (int q = 0; q < 12; q++) { float v = pg[m*96 + h*12 + q]; s += v*v; }
        (m ? g_k2 : g_q2)[h*NN + i] = s;
    }
}

// ---------------------------------------------------------------------------
// kA: logits for one 64-j chunk. grid (512, 8), 256 threads.
// 8-way g-split, 2 j per thread: wb4 LDS amortized.
// ---------------------------------------------------------------------------
__global__ void k_logits(const float* __restrict__ edge,
                         const float* __restrict__ Wb,
                         const float* __restrict__ bb,
                         const float* __restrict__ pw) {
    int i = blockIdx.x, jc = blockIdx.y, j0 = jc * 64;
    int t = threadIdx.x; // 256
    __shared__ float qs_s[128], qp_s[96], q2_s[8], cw_s[8], bb_s[8];
    __shared__ float4 wb4[32*8];
    __shared__ float4 edge_s[64*33];
    __shared__ float pair_red[8][64][9];

    if (t < 128) qs_s[t] = g_qs[i*128 + t];
    else if (t < 224) qp_s[t-128] = g_qp[i*96 + (t-128)];
    else if (t < 232) {
        int h = t - 224;
        q2_s[h] = g_q2[h*NN + i];
        bb_s[h] = bb[h];
        cw_s[h] = 0.5f * POINT_SCALE * log1pf(__expf(pw[h]));
    }
    {
        int eg = t >> 3, h = t & 7;
        wb4[eg*8 + h] = make_float4(Wb[(eg*4+0)*8 + h], Wb[(eg*4+1)*8 + h],
                                    Wb[(eg*4+2)*8 + h], Wb[(eg*4+3)*8 + h]);
    }
    {
        const float4* eg = (const float4*)(edge + ((size_t)i*NN + j0)*EE);
        #pragma unroll 8
        for (int idx = t; idx < 2048; idx += 256)
            edge_s[(idx >> 5)*33 + (idx & 31)] = eg[idx];
    }
    __syncthreads();

    // phase 1: thread (jl2 = t&31, q = t>>5) covers g in [q*4,q*4+4), j in {jl2, jl2+32}
    {
        int jl2 = t & 31, q = t >> 5;
        float p0[8] = {0,0,0,0,0,0,0,0};
        float p1[8] = {0,0,0,0,0,0,0,0};
        #pragma unroll
        for (int gg = 0; gg < 4; gg++) {
            int g = q*4 + gg;
            float4 e0 = edge_s[jl2*33 + g];
            float4 e1 = edge_s[(jl2+32)*33 + g];
            #pragma unroll
            for (int h = 0; h < 8; h++) {
                float4 w = wb4[g*8 + h];
                p0[h] += e0.x*w.x + e0.y*w.y + e0.z*w.z + e0.w*w.w;
                p1[h] += e1.x*w.x + e1.y*w.y + e1.z*w.z + e1.w*w.w;
            }
        }
        #pragma unroll
        for (int h = 0; h < 8; h++) {
            pair_red[q][jl2][h]      = p0[h];
            pair_red[q][jl2+32][h]   = p1[h];
        }
    }
    __syncthreads();

    // phase 2: thread owns (j = t&63, hA = t>>6) and hB = hA+4
    int jl = t & 63, hq = t >> 6;
    int hA = hq, hB = hq + 4;
    float pA = 0.f, pB = 0.f;
    #pragma unroll
    for (int q = 0; q < 8; q++) {
        pA += pair_red[q][jl][hA];
        pB += pair_red[q][jl][hB];
    }
    int j = j0 + jl;
    float sA = 0.f, sB = 0.f;
    #pragma unroll
    for (int k = 0; k < 16; k++) {
        sA += qs_s[hA*16 + k] * g_kkT[(hA*16 + k)*NN + j];
        sB += qs_s[hB*16 + k] * g_kkT[(hB*16 + k)*NN + j];
    }
    float cA = 0.f, cB = 0.f;
    #pragma unroll
    for (int k = 0; k < 12; k++) {
        cA += qp_s[hA*12 + k] * g_kpT[(hA*12 + k)*NN + j];
        cB += qp_s[hB*12 + k] * g_kpT[(hB*12 + k)*NN + j];
    }
    float dA = q2_s[hA] + g_k2[hA*NN + j] - 2.f*cA;
    float dB = q2_s[hB] + g_k2[hB*NN + j] - 2.f*cB;
    g_attn[((size_t)hA*NN + i)*NN + j] =
        SCAL_SCALE*sA - cw_s[hA]*dA + (pA + bb_s[hA])*PAIR_SCALE;
    g_attn[((size_t)hB*NN + i)*NN + j] =
        SCAL_SCALE*sB - cw_s[hB]*dB + (pB + bb_s[hB])*PAIR_SCALE;
}

// ---------------------------------------------------------------------------
// kB: softmax over j. One block per (h,i) row.
// ---------------------------------------------------------------------------
__global__ void k_softmax() {
    size_t row = blockIdx.x;
    float* p = g_attn + row * NN;
    int t = threadIdx.x; // 256
    float a = p[t], b = p[t + 256];
    __shared__ float red[256];
    red[t] = fmaxf(a, b);
    __syncthreads();
    #pragma unroll
    for (int s = 128; s > 0; s >>= 1) {
        if (t < s) red[t] = fmaxf(red[t], red[t + s]);
        __syncthreads();
    }
    float M = red[0];
    __syncthreads();
    float ea = __expf(a - M), eb = __expf(b - M);
    red[t] = ea + eb;
    __syncthreads();
    #pragma unroll
    for (int s = 128; s > 0; s >>= 1) {
        if (t < s) red[t] += red[t + s];
        __syncthreads();
    }
    float inv = 1.f / red[0];
    p[t] = ea * inv;
    p[t + 256] = eb * inv;
}

// ---------------------------------------------------------------------------
// kC: rp partials for one 64-j chunk. grid (512, 8), 256 threads.
// Layout: (e4 0..31, hh 0..1, jg 0..3): 4 heads x 1 f4-col x 16 j per thread.
// ---------------------------------------------------------------------------
__global__ void k_rp(const float* __restrict__ edge) {
    int i = blockIdx.x, jc = blockIdx.y, j0 = jc * 64;
    int t = threadIdx.x;
    int e4 = t & 31, hh = (t >> 5) & 1, jg = t >> 6; // jg 0..3
    __shared__ float lg_s[8*64];
    __shared__ float4 red4[512];

    for (int idx = t; idx < 512; idx += 256)
        lg_s[idx] = g_attn[((size_t)(idx >> 6)*NN + i)*NN + j0 + (idx & 63)];
    __syncthreads();

    float4 acc[4];
    #pragma unroll
    for (int hl = 0; hl < 4; hl++) acc[hl] = make_float4(0.f,0.f,0.f,0.f);

    const float4* ep = (const float4*)(edge + ((size_t)i*NN + j0 + jg*16)*EE) + e4;
    #pragma unroll 8
    for (int jj = 0; jj < 16; jj++) {
        float4 ev = ep[(size_t)jj*32];
        int jrow = jg*16 + jj;
        #pragma unroll
        for (int hl = 0; hl < 4; hl++) {
            float p = lg_s[(hh*4 + hl)*64 + jrow];
            acc[hl].x += ev.x*p; acc[hl].y += ev.y*p;
            acc[hl].z += ev.z*p; acc[hl].w += ev.w*p;
        }
    }
    // reduce jg: {2,3} -> {0,1}
    if (jg >= 2) {
        #pragma unroll
        for (int hl = 0; hl < 4; hl++)
            red4[(((jg-2)*2 + hh)*4 + hl)*32 + e4] = acc[hl];
    }
    __syncthreads();
    if (jg < 2) {
        #pragma unroll
        for (int hl = 0; hl < 4; hl++) {
            float4 o = red4[((jg*2 + hh)*4 + hl)*32 + e4];
            acc[hl].x += o.x; acc[hl].y += o.y; acc[hl].z += o.z; acc[hl].w += o.w;
        }
    }
    __syncthreads();
    // reduce jg: {1} -> {0}
    if (jg == 1) {
        #pragma unroll
        for (int hl = 0; hl < 4; hl++)
            red4[(hh*4 + hl)*32 + e4] = acc[hl];
    }
    __syncthreads();
    if (jg == 0) {
        float4* outp = (float4*)(g_rpp + ((size_t)jc*NN + i)*1024);
        #pragma unroll
        for (int hl = 0; hl < 4; hl++) {
            float4 o = red4[(hh*4 + hl)*32 + e4];
            float4 s = make_float4(acc[hl].x+o.x, acc[hl].y+o.y,
                                   acc[hl].z+o.z, acc[hl].w+o.w);
            outp[(hh*4 + hl)*32 + e4] = s;
        }
    }
}

// ---------------------------------------------------------------------------
// kD: rs / pts / norms + rp reduction -> cat. grid 512, 256 threads.
// ---------------------------------------------------------------------------
__global__ void k_assemble(const float* __restrict__ rot,
                           const float* __restrict__ trans) {
    int i = blockIdx.x, t = threadIdx.x;
    __shared__ float at_s[8*512];
    __shared__ float rs_red[2*128];
    __shared__ float pt_red[2*96];
    __shared__ float pts_s[96];

    for (int idx = t; idx < 4096; idx += 256)
        at_s[idx] = g_attn[((size_t)(idx >> 9)*NN + i)*NN + (idx & 511)];
    __syncthreads();

    float* cat = &g_cat[(size_t)i*CATD];

    {
        int half = t >> 7, c = t & 127, h = c >> 4;
        float a = 0.f;
        #pragma unroll 8
        for (int j = 0; j < 256; j++)
            a += at_s[h*512 + half*256 + j] * g_vs[(size_t)(half*256 + j)*128 + c];
        rs_red[half*128 + c] = a;
    }
    if (t < 192) {
        int half = t / 96, q = t % 96, h = q / 12;
        float a = 0.f;
        #pragma unroll 8
        for (int j = 0; j < 256; j++)
            a += at_s[h*512 + half*256 + j] * g_vp[(size_t)(half*256 + j)*96 + q];
        pt_red[half*96 + q] = a;
    }
    for (int o = t; o < 1024; o += 256) {
        float s = 0.f;
        #pragma unroll
        for (int jc = 0; jc < 8; jc++)
            s += g_rpp[((size_t)jc*NN + i)*1024 + o];
        cat[256 + o] = s;
    }
    __syncthreads();
    if (t < 128) cat[t] = rs_red[t] + rs_red[128 + t];
    else if (t < 224) { int q = t - 128; pts_s[q] = pt_red[q] + pt_red[96 + q]; }
    __syncthreads();

    if (t < 32) {
        int base = t * 3;
        float T0 = trans[i*3], T1 = trans[i*3+1], T2 = trans[i*3+2];
        float x0 = pts_s[base] - T0, x1 = pts_s[base+1] - T1, x2 = pts_s[base+2] - T2;
        const float* R = &rot[i*9];
        float l0 = x0*R[0] + x1*R[1] + x2*R[2];
        float l1 = x0*R[3] + x1*R[4] + x2*R[5];
        float l2 = x0*R[6] + x1*R[7] + x2*R[8];
        cat[128 + base]     = l0;
        cat[128 + base + 1] = l1;
        cat[128 + base + 2] = l2;
        cat[224 + t] = sqrtf(l0*l0 + l1*l1 + l2*l2 + 1e-8f);
    }
}

// ---------------------------------------------------------------------------
// GEMM A (proj only): 32x32 tile, BK=32, 128 threads, 2x4 micro.
// ---------------------------------------------------------------------------
template<int LDX, int NC>
__global__ void k_gemm32(const float* __restrict__ X, const float* __restrict__ W,
                         const float* __restrict__ bias, float* __restrict__ Y, int klen) {
    int r0 = blockIdx.x * 32, c0 = blockIdx.y * 32;
    int t = threadIdx.x;
    __shared__ float Xs[32][33];
    __shared__ float Ws[32][36];

    int tx = t & 7, ty = t >> 3;
    int lrow = t >> 3, lkq = t & 7;

    float acc[2][4];
    #pragma unroll
    for (int a = 0; a < 2; a++)
        #pragma unroll
        for (int b = 0; b < 4; b++) acc[a][b] = 0.f;

    for (int kg = 0; kg < klen; kg += 32) {
        #pragma unroll
        for (int rr = 0; rr < 2; rr++) {
            int row = lrow + rr*16;
            float4 v = *(const float4*)&X[(size_t)(r0 + row)*LDX + kg + lkq*4];
            Xs[lkq*4 + 0][row] = v.x;
            Xs[lkq*4 + 1][row] = v.y;
            Xs[lkq*4 + 2][row] = v.z;
            Xs[lkq*4 + 3][row] = v.w;
        }
        #pragma unroll
        for (int rr = 0; rr < 2; rr++) {
            int k = lrow + rr*16;
            float4 v = *(const float4*)&W[(size_t)(kg + k)*NC + c0 + lkq*4];
            *(float4*)&Ws[k][lkq*4] = v;
        }
        __syncthreads();

        #pragma unroll
        for (int k = 0; k < 32; k++) {
            float x0 = Xs[k][ty*2 + 0];
            float x1 = Xs[k][ty*2 + 1];
            float4 wv = *(const float4*)&Ws[k][tx*4];
            acc[0][0] += x0*wv.x; acc[0][1] += x0*wv.y;
            acc[0][2] += x0*wv.z; acc[0][3] += x0*wv.w;
            acc[1][0] += x1*wv.x; acc[1][1] += x1*wv.y;
            acc[1][2] += x1*wv.z; acc[1][3] += x1*wv.w;
        }
        __syncthreads();
    }

    #pragma unroll
    for (int a = 0; a < 2; a++) {
        int row = r0 + ty*2 + a;
        #pragma unroll
        for (int b = 0; b < 4; b++) {
            int col = c0 + tx*4 + b;
            Y[(size_t)row*NC + col] = acc[a][b] + bias[col];
        }
    }
}

// ---------------------------------------------------------------------------
// GEMM B: 32x64 tile, BK=32, 128 threads, 4x4 micro. Split-K via blockIdx.z.
// ---------------------------------------------------------------------------
template<int LDX, int NC, bool RELU>
__global__ void k_gemm64(const float* __restrict__ X, const float* __restrict__ W,
                         const float* __restrict__ bias,
                         float* __restrict__ Y0, float* __restrict__ Y1,
                         float* __restrict__ Y2, float* __restrict__ Y3, int klen) {
    int r0 = blockIdx.x * 32, c0 = blockIdx.y * 64;
    int z = blockIdx.z;
    int kbase = z * klen;
    float* Y = (z == 0) ? Y0 : (z == 1) ? Y1 : (z == 2) ? Y2 : Y3;
    int t = threadIdx.x;
    __shared__ float Xs[32][36];
    __shared__ float Ws[32][68];

    int tx = t & 15, ty = t >> 4;

    float acc[4][4];
    #pragma unroll
    for (int a = 0; a < 4; a++)
        #pragma unroll
        for (int b = 0; b < 4; b++) acc[a][b] = 0.f;

    int xrow = t >> 2, xk4 = t & 3;
    for (int kc = 0; kc < klen; kc += 32) {
        int kg = kbase + kc;
        #pragma unroll
        for (int hh = 0; hh < 2; hh++) {
            int kq = xk4*2 + hh;
            float4 v = *(const float4*)&X[(size_t)(r0 + xrow)*LDX + kg + kq*4];
            Xs[kq*4 + 0][xrow] = v.x;
            Xs[kq*4 + 1][xrow] = v.y;
            Xs[kq*4 + 2][xrow] = v.z;
            Xs[kq*4 + 3][xrow] = v.w;
        }
        #pragma unroll
        for (int it = 0; it < 4; it++) {
            int idx = t + 128*it;
            int k = idx >> 4, cf4 = idx & 15;
            float4 v = *(const float4*)&W[(size_t)(kg + k)*NC + c0 + cf4*4];
            *(float4*)&Ws[k][cf4*4] = v;
        }
        __syncthreads();

        #pragma unroll
        for (int k = 0; k < 32; k++) {
            float4 xv = *(const float4*)&Xs[k][ty*4];
            float4 wv = *(const float4*)&Ws[k][tx*4];
            acc[0][0] += xv.x*wv.x; acc[0][1] += xv.x*wv.y; acc[0][2] += xv.x*wv.z; acc[0][3] += xv.x*wv.w;
            acc[1][0] += xv.y*wv.x; acc[1][1] += xv.y*wv.y; acc[1][2] += xv.y*wv.z; acc[1][3] += xv.y*wv.w;
            acc[2][0] += xv.z*wv.x; acc[2][1] += xv.z*wv.y; acc[2][2] += xv.z*wv.z; acc[2][3] += xv.z*wv.w;
            acc[3][0] += xv.w*wv.x; acc[3][1] += xv.w*wv.y; acc[3][2] += xv.w*wv.z; acc[3][3] += xv.w*wv.w;
        }
        __syncthreads();
    }

    #pragma unroll
    for (int a = 0; a < 4; a++) {
        int row = r0 + ty*4 + a;
        #pragma unroll
        for (int b = 0; b < 4; b++) {
            int col = c0 + tx*4 + b;
            float v = acc[a][b];
            if (z == 0) v += bias[col];
            if (RELU) v = fmaxf(v, 0.f);
            Y[(size_t)row*NC + col] = v;
        }
    }
}

// ---------------------------------------------------------------------------
// LayerNorm over 384 of (a+b+c+d). 128 threads, 3 elems each.
// ---------------------------------------------------------------------------
__global__ void k_ln4(const float* __restrict__ ia, const float* __restrict__ ib,
                      const float* __restrict__ ic, const float* __restrict__ id,
                      const float* __restrict__ g, const float* __restrict__ b,
                      float* __restrict__ out) {
    int i = blockIdx.x, t = threadIdx.x;
    __shared__ float red[128];
    float v0 = ia[i*DD+t]     + ib[i*DD+t]     + ic[i*DD+t]     + id[i*DD+t];
    float v1 = ia[i*DD+t+128] + ib[i*DD+t+128] + ic[i*DD+t+128] + id[i*DD+t+128];
    float v2 = ia[i*DD+t+256] + ib[i*DD+t+256] + ic[i*DD+t+256] + id[i*DD+t+256];
    red[t] = v0 + v1 + v2;
    __syncthreads();
    #pragma unroll
    for (int s = 64; s > 0; s >>= 1) { if (t < s) red[t] += red[t+s]; __syncthreads(); }
    float mu = red[0] * (1.f/384.f);
    __syncthreads();
    float d0 = v0-mu, d1 = v1-mu, d2 = v2-mu;
    red[t] = d0*d0 + d1*d1 + d2*d2;
    __syncthreads();
    #pragma unroll
    for (int s = 64; s > 0; s >>= 1) { if (t < s) red[t] += red[t+s]; __syncthreads(); }
    float inv = rsqrtf(red[0] * (1.f/384.f) + 1e-5f);
    out[i*DD + t]       = d0*inv*g[t]       + b[t];
    out[i*DD + t + 128] = d1*inv*g[t+128]   + b[t+128];
    out[i*DD + t + 256] = d2*inv*g[t+256]   + b[t+256];
}

// ---------------------------------------------------------------------------
extern "C" void kernel_launch(void* const* d_in, const int* in_sizes, int n_in,
                              void* d_out, int out_size) {
    const float* node  = (const float*)d_in[0];
    const float* edge  = (const float*)d_in[1];
    const float* rot   = (const float*)d_in[2];
    const float* trans = (const float*)d_in[3];
    const float* Wq_s = (const float*)d_in[5];
    const float* Wk_s = (const float*)d_in[6];
    const float* Wv_s = (const float*)d_in[7];
    const float* Wq_p = (const float*)d_in[8];
    const float* Wk_p = (const float*)d_in[9];
    const float* Wv_p = (const float*)d_in[10];
    const float* pw   = (const float*)d_in[11];
    const float* Wb   = (const float*)d_in[12];
    const float* bb   = (const float*)d_in[13];
    const float* Wo   = (const float*)d_in[14];
    const float* bo   = (const float*)d_in[15];
    const float* g1   = (const float*)d_in[16];
    const float* beta1= (const float*)d_in[17];
    const float* W1   = (const float*)d_in[18];
    const float* b1   = (const float*)d_in[19];
    const float* W2   = (const float*)d_in[20];
    const float* b2   = (const float*)d_in[21];
    const float* W3   = (const float*)d_in[22];
    const float* b3   = (const float*)d_in[23];
    const float* g2   = (const float*)d_in[24];
    const float* beta2= (const float*)d_in[25];
    float* out = (float*)d_out;

    float *p_cat, *p_t0, *p_t1, *p_t2, *p_t3, *p_x1, *p_h1, *p_h2;
    float *p_Wall, *p_zero, *p_proj;
    cudaGetSymbolAddress((void**)&p_cat, g_cat);
    cudaGetSymbolAddress((void**)&p_t0, g_t0);
    cudaGetSymbolAddress((void**)&p_t1, g_t1);
    cudaGetSymbolAddress((void**)&p_t2, g_t2);
    cudaGetSymbolAddress((void**)&p_t3, g_t3);
    cudaGetSymbolAddress((void**)&p_x1, g_x1);
    cudaGetSymbolAddress((void**)&p_h1, g_h1);
    cudaGetSymbolAddress((void**)&p_h2, g_h2);
    cudaGetSymbolAddress((void**)&p_Wall, g_Wall);
    cudaGetSymbolAddress((void**)&p_zero, g_zero);
    cudaGetSymbolAddress((void**)&p_proj, g_proj);

    k_packW<<<(DD*PCOLS + 255)/256, 256>>>(Wq_s, Wk_s, Wv_s, Wq_p, Wk_p, Wv_p);
    k_gemm32<DD, PCOLS><<<dim3(16, 21), 128>>>(node, p_Wall, p_zero, p_proj, DD);
    k_post<<<NN, 128>>>(rot, trans);
    k_logits<<<dim3(NN, 8), 256>>>(edge, Wb, bb, pw);
    k_softmax<<<HH*NN, 256>>>();
    k_rp<<<dim3(NN, 8), 256>>>(edge);
    k_assemble<<<NN, 256>>>(rot, trans);

    // Wo: split-K 4 x 320
    k_gemm64<CATD, DD, false><<<dim3(16, 6, 4), 128>>>(p_cat, Wo, bo, p_t0, p_t1, p_t2, p_t3, 320);
    k_ln4<<<NN, 128>>>(p_t0, p_t1, p_t2, p_t3, g1, beta1, p_x1);
    // MLP
    k_gemm64<DD, HID, true><<<dim3(16, 12, 1), 128>>>(p_x1, W1, b1, p_h1, p_h1, p_h1, p_h1, 384);
    k_gemm64<HID, HID, true><<<dim3(16, 12, 1), 128>>>(p_h1, W2, b2, p_h2, p_h2, p_h2, p_h2, 768);
    // W3: split-K 4 x 192
    k_gemm64<HID, DD, false><<<dim3(16, 6, 4), 128>>>(p_h2, W3, b3, p_t0, p_t1, p_t2, p_t3, 192);
    k_ln4<<<NN, 128>>>(p_t0, p_t1, p_t2, p_t3, g2, beta2, out);
}

// round 9
// speedup vs baseline: 2.9404x; 1.0465x over previous
#include <cuda_runtime.h>
#include <cuda_bf16.h>
#include <math.h>

#define NN 512
#define DD 384
#define EE 128
#define HH 8
#define CATD 1280
#define HID 768
#define PCOLS 672

static __device__ __constant__ float SCAL_SCALE = 0.14433756729740643f; // (3*16)^-0.5
static __device__ __constant__ float POINT_SCALE = 0.13608276348795434f; // (3*4*4.5)^-0.5
static __device__ __constant__ float PAIR_SCALE = 0.5773502691896258f;  // 3^-0.5

// scratch
__device__ float g_Wall[DD*PCOLS];
__device__ float g_zero[PCOLS];
__device__ float g_proj[NN*PCOLS];
__device__ float g_qs[NN*128];
__device__ float g_kkT[128*NN];   // [h*16+k][j]
__device__ float g_vs[NN*128];
__device__ float g_qp[NN*96];
__device__ float g_kpT[96*NN];    // [h*12+q][j]
__device__ float g_vp[NN*96];
__device__ float g_q2[HH*NN];
__device__ float g_k2[HH*NN];
__device__ float g_attn[(size_t)HH*NN*NN];   // RAW logits
__device__ float g_m[HH*NN];                 // row max
__device__ float g_inv[HH*NN];               // 1 / row sumexp
__device__ float g_rpp[(size_t)8*NN*1024];   // rp partials [jc][i][h*128+e]
__device__ float g_cat[(size_t)NN*CATD];
__device__ float g_t0[NN*DD];
__device__ float g_t1[NN*DD];
__device__ float g_t2[NN*DD];
__device__ float g_t3[NN*DD];
__device__ float g_x1[NN*DD];
__device__ float g_h1[NN*HID];
__device__ float g_h2[NN*HID];

// ---------------------------------------------------------------------------
// K0: pack projection weights into one [384 x 672] matrix + zero bias
// ---------------------------------------------------------------------------
__global__ void k_packW(const float* __restrict__ Wq_s, const float* __restrict__ Wk_s,
                        const float* __restrict__ Wv_s,
                        const float* __restrict__ Wq_p, const float* __restrict__ Wk_p,
                        const float* __restrict__ Wv_p) {
    int idx = blockIdx.x * 256 + threadIdx.x;
    if (idx < PCOLS) g_zero[idx] = 0.f;
    if (idx >= DD*PCOLS) return;
    int r = idx / PCOLS, c = idx % PCOLS;
    float v;
    if (c < 128)      v = Wq_s[r*128 + c];
    else if (c < 256) v = Wk_s[r*128 + (c-128)];
    else if (c < 384) v = Wv_s[r*128 + (c-256)];
    else if (c < 480) v = Wq_p[r*96 + (c-384)];
    else if (c < 576) v = Wk_p[r*96 + (c-480)];
    else              v = Wv_p[r*96 + (c-576)];
    g_Wall[idx] = v;
}

// ---------------------------------------------------------------------------
// K_post: scatter proj results, rigid transforms, q2/k2. One block per i.
// ---------------------------------------------------------------------------
__global__ void k_post(const float* __restrict__ rot,
                       const float* __restrict__ trans) {
    int i = blockIdx.x, t = threadIdx.x; // 128
    __shared__ float pg[192];
    const float* pr = &g_proj[i*PCOLS];

    float a = pr[t];
    g_qs[i*128 + t] = a;
    g_kkT[t*NN + i] = pr[128 + t];
    g_vs[i*128 + t] = pr[256 + t];

    const float* R = &rot[i*9];
    float T[3] = {trans[i*3], trans[i*3+1], trans[i*3+2]};
    for (int q = t; q < 288; q += 128) {
        int m = q / 96, qq = q % 96;
        int hd = qq / 3, rr = qq % 3;
        float v = T[rr];
        #pragma unroll
        for (int c = 0; c < 3; c++) v += pr[384 + m*96 + hd*3 + c] * R[c*3 + rr];
        if (m == 0)      { g_qp[i*96 + qq] = v; pg[qq] = v; }
        else if (m == 1) { g_kpT[qq*NN + i] = v; pg[96 + qq] = v; }
        else               g_vp[i*96 + qq] = v;
    }
    __syncthreads();

    if (t < 16) {
        int m = t >> 3, h = t & 7;
        float s = 0.f;
        #pragma unroll
        for (int q = 0; q < 12; q++) { float v = pg[m*96 + h*12 + q]; s += v*v; }
        (m ? g_k2 : g_q2)[h*NN + i] = s;
    }
}

// ---------------------------------------------------------------------------
// kA: raw logits for one 32-j chunk. grid (512, 16), 256 threads.
// Small smem footprint -> high occupancy.
// ---------------------------------------------------------------------------
__global__ void __launch_bounds__(256) k_logits(const float* __restrict__ edge,
                         const float* __restrict__ Wb,
                         const float* __restrict__ bb,
                         const float* __restrict__ pw) {
    int i = blockIdx.x, jc = blockIdx.y, j0 = jc * 32;
    int t = threadIdx.x; // 256
    __shared__ float qs_s[128], qp_s[96], q2_s[8], cw_s[8], bb_s[8];
    __shared__ float4 wb4[32*8];       // 4 KB
    __shared__ float4 edge_s[32*33];   // 16.9 KB
    __shared__ float pair_red[8][32][9]; // 9.2 KB

    if (t < 128) qs_s[t] = g_qs[i*128 + t];
    else if (t < 224) qp_s[t-128] = g_qp[i*96 + (t-128)];
    else if (t < 232) {
        int h = t - 224;
        q2_s[h] = g_q2[h*NN + i];
        bb_s[h] = bb[h];
        cw_s[h] = 0.5f * POINT_SCALE * log1pf(__expf(pw[h]));
    }
    {
        int eg = t >> 3, h = t & 7;
        wb4[eg*8 + h] = make_float4(Wb[(eg*4+0)*8 + h], Wb[(eg*4+1)*8 + h],
                                    Wb[(eg*4+2)*8 + h], Wb[(eg*4+3)*8 + h]);
    }
    {
        const float4* eg = (const float4*)(edge + ((size_t)i*NN + j0)*EE);
        #pragma unroll
        for (int idx = t; idx < 1024; idx += 256)
            edge_s[(idx >> 5)*33 + (idx & 31)] = eg[idx];
    }
    __syncthreads();

    // phase 1: thread (jl = t&31, q = t>>5) covers g in [q*4, q*4+4), one j
    {
        int jl = t & 31, q = t >> 5;
        float p[8] = {0,0,0,0,0,0,0,0};
        #pragma unroll
        for (int gg = 0; gg < 4; gg++) {
            int g = q*4 + gg;
            float4 e = edge_s[jl*33 + g];
            #pragma unroll
            for (int h = 0; h < 8; h++) {
                float4 w = wb4[g*8 + h];
                p[h] += e.x*w.x + e.y*w.y + e.z*w.z + e.w*w.w;
            }
        }
        #pragma unroll
        for (int h = 0; h < 8; h++) pair_red[q][jl][h] = p[h];
    }
    __syncthreads();

    // phase 2: thread owns (j = t&31, h = t>>5)
    {
        int jl = t & 31, h = t >> 5;
        float pb = 0.f;
        #pragma unroll
        for (int q = 0; q < 8; q++) pb += pair_red[q][jl][h];
        int j = j0 + jl;
        float s = 0.f;
        #pragma unroll
        for (int k = 0; k < 16; k++)
            s += qs_s[h*16 + k] * g_kkT[(h*16 + k)*NN + j];
        float c = 0.f;
        #pragma unroll
        for (int k = 0; k < 12; k++)
            c += qp_s[h*12 + k] * g_kpT[(h*12 + k)*NN + j];
        float d = q2_s[h] + g_k2[h*NN + j] - 2.f*c;
        g_attn[((size_t)h*NN + i)*NN + j] =
            SCAL_SCALE*s - cw_s[h]*d + (pb + bb_s[h])*PAIR_SCALE;
    }
}

// ---------------------------------------------------------------------------
// kB: per-row (max, 1/sumexp). One block per (h,i) row, 128 threads.
// ---------------------------------------------------------------------------
__global__ void k_stats() {
    size_t row = blockIdx.x;
    const float* p = g_attn + row * NN;
    int t = threadIdx.x; // 128
    float v0 = p[t], v1 = p[t+128], v2 = p[t+256], v3 = p[t+384];
    __shared__ float red[128];
    red[t] = fmaxf(fmaxf(v0, v1), fmaxf(v2, v3));
    __syncthreads();
    #pragma unroll
    for (int s = 64; s > 0; s >>= 1) {
        if (t < s) red[t] = fmaxf(red[t], red[t+s]);
        __syncthreads();
    }
    float M = red[0];
    __syncthreads();
    red[t] = __expf(v0-M) + __expf(v1-M) + __expf(v2-M) + __expf(v3-M);
    __syncthreads();
    #pragma unroll
    for (int s = 64; s > 0; s >>= 1) {
        if (t < s) red[t] += red[t+s];
        __syncthreads();
    }
    if (t == 0) { g_m[row] = M; g_inv[row] = 1.f / red[0]; }
}

// ---------------------------------------------------------------------------
// kC: rp partials for one 64-j chunk. grid (512, 8), 256 threads.
// REVERSED block order so first reads hit edge rows still hot in L2.
// ---------------------------------------------------------------------------
__global__ void k_rp(const float* __restrict__ edge) {
    int i = (NN-1) - blockIdx.x, jc = 7 - blockIdx.y, j0 = jc * 64;
    int t = threadIdx.x;
    int e4 = t & 31, hh = (t >> 5) & 1, jg = t >> 6; // jg 0..3
    __shared__ float lg_s[8*64];
    __shared__ float4 red4[512];
    __shared__ float m_s[8], v_s[8];

    if (t < 8) { m_s[t] = g_m[t*NN + i]; v_s[t] = g_inv[t*NN + i]; }
    __syncthreads();

    for (int idx = t; idx < 512; idx += 256) {
        int h = idx >> 6;
        float raw = g_attn[((size_t)h*NN + i)*NN + j0 + (idx & 63)];
        lg_s[idx] = __expf(raw - m_s[h]) * v_s[h];
    }
    __syncthreads();

    float4 acc[4];
    #pragma unroll
    for (int hl = 0; hl < 4; hl++) acc[hl] = make_float4(0.f,0.f,0.f,0.f);

    const float4* ep = (const float4*)(edge + ((size_t)i*NN + j0 + jg*16)*EE) + e4;
    #pragma unroll 8
    for (int jj = 0; jj < 16; jj++) {
        float4 ev = ep[(size_t)jj*32];
        int jrow = jg*16 + jj;
        #pragma unroll
        for (int hl = 0; hl < 4; hl++) {
            float p = lg_s[(hh*4 + hl)*64 + jrow];
            acc[hl].x += ev.x*p; acc[hl].y += ev.y*p;
            acc[hl].z += ev.z*p; acc[hl].w += ev.w*p;
        }
    }
    if (jg >= 2) {
        #pragma unroll
        for (int hl = 0; hl < 4; hl++)
            red4[(((jg-2)*2 + hh)*4 + hl)*32 + e4] = acc[hl];
    }
    __syncthreads();
    if (jg < 2) {
        #pragma unroll
        for (int hl = 0; hl < 4; hl++) {
            float4 o = red4[((jg*2 + hh)*4 + hl)*32 + e4];
            acc[hl].x += o.x; acc[hl].y += o.y; acc[hl].z += o.z; acc[hl].w += o.w;
        }
    }
    __syncthreads();
    if (jg == 1) {
        #pragma unroll
        for (int hl = 0; hl < 4; hl++)
            red4[(hh*4 + hl)*32 + e4] = acc[hl];
    }
    __syncthreads();
    if (jg == 0) {
        float4* outp = (float4*)(g_rpp + ((size_t)jc*NN + i)*1024);
        #pragma unroll
        for (int hl = 0; hl < 4; hl++) {
            float4 o = red4[(hh*4 + hl)*32 + e4];
            outp[(hh*4 + hl)*32 + e4] = make_float4(acc[hl].x+o.x, acc[hl].y+o.y,
                                                    acc[hl].z+o.z, acc[hl].w+o.w);
        }
    }
}

// ---------------------------------------------------------------------------
// kD: rs / pts / norms + rp reduction -> cat. grid 512, 256 threads.
// ---------------------------------------------------------------------------
__global__ void k_assemble(const float* __restrict__ rot,
                           const float* __restrict__ trans) {
    int i = blockIdx.x, t = threadIdx.x;
    __shared__ float at_s[8*512];
    __shared__ float rs_red[2*128];
    __shared__ float pt_red[2*96];
    __shared__ float pts_s[96];
    __shared__ float m_s[8], v_s[8];

    if (t < 8) { m_s[t] = g_m[t*NN + i]; v_s[t] = g_inv[t*NN + i]; }
    __syncthreads();

    for (int idx = t; idx < 4096; idx += 256) {
        int h = idx >> 9;
        float raw = g_attn[((size_t)h*NN + i)*NN + (idx & 511)];
        at_s[idx] = __expf(raw - m_s[h]) * v_s[h];
    }
    __syncthreads();

    float* cat = &g_cat[(size_t)i*CATD];

    {
        int half = t >> 7, c = t & 127, h = c >> 4;
        float a = 0.f;
        #pragma unroll 8
        for (int j = 0; j < 256; j++)
            a += at_s[h*512 + half*256 + j] * g_vs[(size_t)(half*256 + j)*128 + c];
        rs_red[half*128 + c] = a;
    }
    if (t < 192) {
        int half = t / 96, q = t % 96, h = q / 12;
        float a = 0.f;
        #pragma unroll 8
        for (int j = 0; j < 256; j++)
            a += at_s[h*512 + half*256 + j] * g_vp[(size_t)(half*256 + j)*96 + q];
        pt_red[half*96 + q] = a;
    }
    for (int o = t; o < 1024; o += 256) {
        float s = 0.f;
        #pragma unroll
        for (int jc = 0; jc < 8; jc++)
            s += g_rpp[((size_t)jc*NN + i)*1024 + o];
        cat[256 + o] = s;
    }
    __syncthreads();
    if (t < 128) cat[t] = rs_red[t] + rs_red[128 + t];
    else if (t < 224) { int q = t - 128; pts_s[q] = pt_red[q] + pt_red[96 + q]; }
    __syncthreads();

    if (t < 32) {
        int base = t * 3;
        float T0 = trans[i*3], T1 = trans[i*3+1], T2 = trans[i*3+2];
        float x0 = pts_s[base] - T0, x1 = pts_s[base+1] - T1, x2 = pts_s[base+2] - T2;
        const float* R = &rot[i*9];
        float l0 = x0*R[0] + x1*R[1] + x2*R[2];
        float l1 = x0*R[3] + x1*R[4] + x2*R[5];
        float l2 = x0*R[6] + x1*R[7] + x2*R[8];
        cat[128 + base]     = l0;
        cat[128 + base + 1] = l1;
        cat[128 + base + 2] = l2;
        cat[224 + t] = sqrtf(l0*l0 + l1*l1 + l2*l2 + 1e-8f);
    }
}

// ---------------------------------------------------------------------------
// GEMM A (proj only): 32x32 tile, BK=32, 128 threads, 2x4 micro.
// ---------------------------------------------------------------------------
template<int LDX, int NC>
__global__ void k_gemm32(const float* __restrict__ X, const float* __restrict__ W,
                         const float* __restrict__ bias, float* __restrict__ Y, int klen) {
    int r0 = blockIdx.x * 32, c0 = blockIdx.y * 32;
    int t = threadIdx.x;
    __shared__ float Xs[32][33];
    __shared__ float Ws[32][36];

    int tx = t & 7, ty = t >> 3;
    int lrow = t >> 3, lkq = t & 7;

    float acc[2][4];
    #pragma unroll
    for (int a = 0; a < 2; a++)
        #pragma unroll
        for (int b = 0; b < 4; b++) acc[a][b] = 0.f;

    for (int kg = 0; kg < klen; kg += 32) {
        #pragma unroll
        for (int rr = 0; rr < 2; rr++) {
            int row = lrow + rr*16;
            float4 v = *(const float4*)&X[(size_t)(r0 + row)*LDX + kg + lkq*4];
            Xs[lkq*4 + 0][row] = v.x;
            Xs[lkq*4 + 1][row] = v.y;
            Xs[lkq*4 + 2][row] = v.z;
            Xs[lkq*4 + 3][row] = v.w;
        }
        #pragma unroll
        for (int rr = 0; rr < 2; rr++) {
            int k = lrow + rr*16;
            float4 v = *(const float4*)&W[(size_t)(kg + k)*NC + c0 + lkq*4];
            *(float4*)&Ws[k][lkq*4] = v;
        }
        __syncthreads();

        #pragma unroll
        for (int k = 0; k < 32; k++) {
            float x0 = Xs[k][ty*2 + 0];
            float x1 = Xs[k][ty*2 + 1];
            float4 wv = *(const float4*)&Ws[k][tx*4];
            acc[0][0] += x0*wv.x; acc[0][1] += x0*wv.y;
            acc[0][2] += x0*wv.z; acc[0][3] += x0*wv.w;
            acc[1][0] += x1*wv.x; acc[1][1] += x1*wv.y;
            acc[1][2] += x1*wv.z; acc[1][3] += x1*wv.w;
        }
        __syncthreads();
    }

    #pragma unroll
    for (int a = 0; a < 2; a++) {
        int row = r0 + ty*2 + a;
        #pragma unroll
        for (int b = 0; b < 4; b++) {
            int col = c0 + tx*4 + b;
            Y[(size_t)row*NC + col] = acc[a][b] + bias[col];
        }
    }
}

// ---------------------------------------------------------------------------
// GEMM B: 32x64 tile, BK=32, 128 threads, 4x4 micro. Split-K via blockIdx.z.
// ---------------------------------------------------------------------------
template<int LDX, int NC, bool RELU>
__global__ void k_gemm64(const float* __restrict__ X, const float* __restrict__ W,
                         const float* __restrict__ bias,
                         float* __restrict__ Y0, float* __restrict__ Y1,
                         float* __restrict__ Y2, float* __restrict__ Y3, int klen) {
    int r0 = blockIdx.x * 32, c0 = blockIdx.y * 64;
    int z = blockIdx.z;
    int kbase = z * klen;
    float* Y = (z == 0) ? Y0 : (z == 1) ? Y1 : (z == 2) ? Y2 : Y3;
    int t = threadIdx.x;
    __shared__ float Xs[32][36];
    __shared__ float Ws[32][68];

    int tx = t & 15, ty = t >> 4;

    float acc[4][4];
    #pragma unroll
    for (int a = 0; a < 4; a++)
        #pragma unroll
        for (int b = 0; b < 4; b++) acc[a][b] = 0.f;

    int xrow = t >> 2, xk4 = t & 3;
    for (int kc = 0; kc < klen; kc += 32) {
        int kg = kbase + kc;
        #pragma unroll
        for (int hh = 0; hh < 2; hh++) {
            int kq = xk4*2 + hh;
            float4 v = *(const float4*)&X[(size_t)(r0 + xrow)*LDX + kg + kq*4];
            Xs[kq*4 + 0][xrow] = v.x;
            Xs[kq*4 + 1][xrow] = v.y;
            Xs[kq*4 + 2][xrow] = v.z;
            Xs[kq*4 + 3][xrow] = v.w;
        }
        #pragma unroll
        for (int it = 0; it < 4; it++) {
            int idx = t + 128*it;
            int k = idx >> 4, cf4 = idx & 15;
            float4 v = *(const float4*)&W[(size_t)(kg + k)*NC + c0 + cf4*4];
            *(float4*)&Ws[k][cf4*4] = v;
        }
        __syncthreads();

        #pragma unroll
        for (int k = 0; k < 32; k++) {
            float4 xv = *(const float4*)&Xs[k][ty*4];
            float4 wv = *(const float4*)&Ws[k][tx*4];
            acc[0][0] += xv.x*wv.x; acc[0][1] += xv.x*wv.y; acc[0][2] += xv.x*wv.z; acc[0][3] += xv.x*wv.w;
            acc[1][0] += xv.y*wv.x; acc[1][1] += xv.y*wv.y; acc[1][2] += xv.y*wv.z; acc[1][3] += xv.y*wv.w;
            acc[2][0] += xv.z*wv.x; acc[2][1] += xv.z*wv.y; acc[2][2] += xv.z*wv.z; acc[2][3] += xv.z*wv.w;
            acc[3][0] += xv.w*wv.x; acc[3][1] += xv.w*wv.y; acc[3][2] += xv.w*wv.z; acc[3][3] += xv.w*wv.w;
        }
        __syncthreads();
    }

    #pragma unroll
    for (int a = 0; a < 4; a++) {
        int row = r0 + ty*4 + a;
        #pragma unroll
        for (int b = 0; b < 4; b++) {
            int col = c0 + tx*4 + b;
            float v = acc[a][b];
            if (z == 0) v += bias[col];
            if (RELU) v = fmaxf(v, 0.f);
            Y[(size_t)row*NC + col] = v;
        }
    }
}

// ---------------------------------------------------------------------------
// LayerNorm over 384 of (a+b+c+d). 128 threads, 3 elems each.
// ---------------------------------------------------------------------------
__global__ void k_ln4(const float* __restrict__ ia, const float* __restrict__ ib,
                      const float* __restrict__ ic, const float* __restrict__ id,
                      const float* __restrict__ g, const float* __restrict__ b,
                      float* __restrict__ out) {
    int i = blockIdx.x, t = threadIdx.x;
    __shared__ float red[128];
    float v0 = ia[i*DD+t]     + ib[i*DD+t]     + ic[i*DD+t]     + id[i*DD+t];
    float v1 = ia[i*DD+t+128] + ib[i*DD+t+128] + ic[i*DD+t+128] + id[i*DD+t+128];
    float v2 = ia[i*DD+t+256] + ib[i*DD+t+256] + ic[i*DD+t+256] + id[i*DD+t+256];
    red[t] = v0 + v1 + v2;
    __syncthreads();
    #pragma unroll
    for (int s = 64; s > 0; s >>= 1) { if (t < s) red[t] += red[t+s]; __syncthreads(); }
    float mu = red[0] * (1.f/384.f);
    __syncthreads();
    float d0 = v0-mu, d1 = v1-mu, d2 = v2-mu;
    red[t] = d0*d0 + d1*d1 + d2*d2;
    __syncthreads();
    #pragma unroll
    for (int s = 64; s > 0; s >>= 1) { if (t < s) red[t] += red[t+s]; __syncthreads(); }
    float inv = rsqrtf(red[0] * (1.f/384.f) + 1e-5f);
    out[i*DD + t]       = d0*inv*g[t]       + b[t];
    out[i*DD + t + 128] = d1*inv*g[t+128]   + b[t+128];
    out[i*DD + t + 256] = d2*inv*g[t+256]   + b[t+256];
}

// ---------------------------------------------------------------------------
extern "C" void kernel_launch(void* const* d_in, const int* in_sizes, int n_in,
                              void* d_out, int out_size) {
    const float* node  = (const float*)d_in[0];
    const float* edge  = (const float*)d_in[1];
    const float* rot   = (const float*)d_in[2];
    const float* trans = (const float*)d_in[3];
    const float* Wq_s = (const float*)d_in[5];
    const float* Wk_s = (const float*)d_in[6];
    const float* Wv_s = (const float*)d_in[7];
    const float* Wq_p = (const float*)d_in[8];
    const float* Wk_p = (const float*)d_in[9];
    const float* Wv_p = (const float*)d_in[10];
    const float* pw   = (const float*)d_in[11];
    const float* Wb   = (const float*)d_in[12];
    const float* bb   = (const float*)d_in[13];
    const float* Wo   = (const float*)d_in[14];
    const float* bo   = (const float*)d_in[15];
    const float* g1   = (const float*)d_in[16];
    const float* beta1= (const float*)d_in[17];
    const float* W1   = (const float*)d_in[18];
    const float* b1   = (const float*)d_in[19];
    const float* W2   = (const float*)d_in[20];
    const float* b2   = (const float*)d_in[21];
    const float* W3   = (const float*)d_in[22];
    const float* b3   = (const float*)d_in[23];
    const float* g2   = (const float*)d_in[24];
    const float* beta2= (const float*)d_in[25];
    float* out = (float*)d_out;

    float *p_cat, *p_t0, *p_t1, *p_t2, *p_t3, *p_x1, *p_h1, *p_h2;
    float *p_Wall, *p_zero, *p_proj;
    cudaGetSymbolAddress((void**)&p_cat, g_cat);
    cudaGetSymbolAddress((void**)&p_t0, g_t0);
    cudaGetSymbolAddress((void**)&p_t1, g_t1);
    cudaGetSymbolAddress((void**)&p_t2, g_t2);
    cudaGetSymbolAddress((void**)&p_t3, g_t3);
    cudaGetSymbolAddress((void**)&p_x1, g_x1);
    cudaGetSymbolAddress((void**)&p_h1, g_h1);
    cudaGetSymbolAddress((void**)&p_h2, g_h2);
    cudaGetSymbolAddress((void**)&p_Wall, g_Wall);
    cudaGetSymbolAddress((void**)&p_zero, g_zero);
    cudaGetSymbolAddress((void**)&p_proj, g_proj);

    k_packW<<<(DD*PCOLS + 255)/256, 256>>>(Wq_s, Wk_s, Wv_s, Wq_p, Wk_p, Wv_p);
    k_gemm32<DD, PCOLS><<<dim3(16, 21), 128>>>(node, p_Wall, p_zero, p_proj, DD);
    k_post<<<NN, 128>>>(rot, trans);
    k_logits<<<dim3(NN, 16), 256>>>(edge, Wb, bb, pw);
    k_stats<<<HH*NN, 128>>>();
    k_rp<<<dim3(NN, 8), 256>>>(edge);
    k_assemble<<<NN, 256>>>(rot, trans);

    // Wo: split-K 4 x 320
    k_gemm64<CATD, DD, false><<<dim3(16, 6, 4), 128>>>(p_cat, Wo, bo, p_t0, p_t1, p_t2, p_t3, 320);
    k_ln4<<<NN, 128>>>(p_t0, p_t1, p_t2, p_t3, g1, beta1, p_x1);
    // MLP
    k_gemm64<DD, HID, true><<<dim3(16, 12, 1), 128>>>(p_x1, W1, b1, p_h1, p_h1, p_h1, p_h1, 384);
    k_gemm64<HID, HID, true><<<dim3(16, 12, 1), 128>>>(p_h1, W2, b2, p_h2, p_h2, p_h2, p_h2, 768);
    // W3: split-K 4 x 192
    k_gemm64<HID, DD, false><<<dim3(16, 6, 4), 128>>>(p_h2, W3, b3, p_t0, p_t1, p_t2, p_t3, 192);
    k_ln4<<<NN, 128>>>(p_t0, p_t1, p_t2, p_t3, g2, beta2, out);
}

// round 10
// speedup vs baseline: 3.2272x; 1.0975x over previous
#include <cuda_runtime.h>
#include <cuda_bf16.h>
#include <math.h>

#define NN 512
#define DD 384
#define EE 128
#define HH 8
#define CATD 1280
#define HID 768
#define PCOLS 672

static __device__ __constant__ float SCAL_SCALE = 0.14433756729740643f; // (3*16)^-0.5
static __device__ __constant__ float POINT_SCALE = 0.13608276348795434f; // (3*4*4.5)^-0.5
static __device__ __constant__ float PAIR_SCALE = 0.5773502691896258f;  // 3^-0.5

// scratch
__device__ float g_Wall[DD*PCOLS];
__device__ float g_zero[PCOLS];
__device__ float g_proj[NN*PCOLS];
__device__ float g_qs[NN*128];
__device__ float g_kkT[128*NN];   // [h*16+k][j]
__device__ float g_vs[NN*128];
__device__ float g_qp[NN*96];
__device__ float g_kpT[96*NN];    // [h*12+q][j]
__device__ float g_vp[NN*96];
__device__ float g_q2[HH*NN];
__device__ float g_k2[HH*NN];
__device__ float g_attn[(size_t)HH*NN*NN];   // exp(raw - m_chunk)
__device__ float g_mc[HH*NN*8];              // chunk max   [h][i*8+jc]
__device__ float g_sc[HH*NN*8];              // chunk sum   [h][i*8+jc]
__device__ float g_rpp[(size_t)8*NN*1024];   // rp partials [jc][i][h*128+e]
__device__ float g_cat[(size_t)NN*CATD];
__device__ float g_t0[NN*DD];
__device__ float g_t1[NN*DD];
__device__ float g_t2[NN*DD];
__device__ float g_t3[NN*DD];
__device__ float g_x1[NN*DD];
__device__ float g_h1[NN*HID];
__device__ float g_h2[NN*HID];

// ---------------------------------------------------------------------------
// K0: pack projection weights into one [384 x 672] matrix + zero bias
// ---------------------------------------------------------------------------
__global__ void k_packW(const float* __restrict__ Wq_s, const float* __restrict__ Wk_s,
                        const float* __restrict__ Wv_s,
                        const float* __restrict__ Wq_p, const float* __restrict__ Wk_p,
                        const float* __restrict__ Wv_p) {
    int idx = blockIdx.x * 256 + threadIdx.x;
    if (idx < PCOLS) g_zero[idx] = 0.f;
    if (idx >= DD*PCOLS) return;
    int r = idx / PCOLS, c = idx % PCOLS;
    float v;
    if (c < 128)      v = Wq_s[r*128 + c];
    else if (c < 256) v = Wk_s[r*128 + (c-128)];
    else if (c < 384) v = Wv_s[r*128 + (c-256)];
    else if (c < 480) v = Wq_p[r*96 + (c-384)];
    else if (c < 576) v = Wk_p[r*96 + (c-480)];
    else              v = Wv_p[r*96 + (c-576)];
    g_Wall[idx] = v;
}

// ---------------------------------------------------------------------------
// K_post: scatter proj results, rigid transforms, q2/k2. One block per i.
// ---------------------------------------------------------------------------
__global__ void k_post(const float* __restrict__ rot,
                       const float* __restrict__ trans) {
    int i = blockIdx.x, t = threadIdx.x; // 128
    __shared__ float pg[192];
    const float* pr = &g_proj[i*PCOLS];

    float a = pr[t];
    g_qs[i*128 + t] = a;
    g_kkT[t*NN + i] = pr[128 + t];
    g_vs[i*128 + t] = pr[256 + t];

    const float* R = &rot[i*9];
    float T[3] = {trans[i*3], trans[i*3+1], trans[i*3+2]};
    for (int q = t; q < 288; q += 128) {
        int m = q / 96, qq = q % 96;
        int hd = qq / 3, rr = qq % 3;
        float v = T[rr];
        #pragma unroll
        for (int c = 0; c < 3; c++) v += pr[384 + m*96 + hd*3 + c] * R[c*3 + rr];
        if (m == 0)      { g_qp[i*96 + qq] = v; pg[qq] = v; }
        else if (m == 1) { g_kpT[qq*NN + i] = v; pg[96 + qq] = v; }
        else               g_vp[i*96 + qq] = v;
    }
    __syncthreads();

    if (t < 16) {
        int m = t >> 3, h = t & 7;
        float s = 0.f;
        #pragma unroll
        for (int q = 0; q < 12; q++) { float v = pg[m*96 + h*12 + q]; s += v*v; }
        (m ? g_k2 : g_q2)[h*NN + i] = s;
    }
}

// ---------------------------------------------------------------------------
// k_fused: ONE edge pass. Per (i, 64-j chunk): logits + chunk softmax stats
// + exp store + rp partial accumulation. grid (512, 8), 256 threads.
// ---------------------------------------------------------------------------
__global__ void __launch_bounds__(256) k_fused(const float* __restrict__ edge,
                        const float* __restrict__ Wb,
                        const float* __restrict__ bb,
                        const float* __restrict__ pw) {
    int i = blockIdx.x, jc = blockIdx.y, j0 = jc * 64;
    int t = threadIdx.x; // 256

    __shared__ float4 edge_s[64*33];     // 33.8 KB
    __shared__ float4 wb4[32*8];         // 4 KB
    __shared__ float lg[8*64];           // 2 KB: raw logits, then exp values
    __shared__ float qs_s[128], qp_s[96], q2_s[8], cw_s[8], bb_s[8];
    __shared__ float scratch[2304];      // 9.2 KB: pair_red (phase B) / red4 (phase D)

    if (t < 128) qs_s[t] = g_qs[i*128 + t];
    else if (t < 224) qp_s[t-128] = g_qp[i*96 + (t-128)];
    else if (t < 232) {
        int h = t - 224;
        q2_s[h] = g_q2[h*NN + i];
        bb_s[h] = bb[h];
        cw_s[h] = 0.5f * POINT_SCALE * log1pf(__expf(pw[h]));
    }
    {
        int eg = t >> 3, h = t & 7;
        wb4[eg*8 + h] = make_float4(Wb[(eg*4+0)*8 + h], Wb[(eg*4+1)*8 + h],
                                    Wb[(eg*4+2)*8 + h], Wb[(eg*4+3)*8 + h]);
    }
    {
        const float4* eg = (const float4*)(edge + ((size_t)i*NN + j0)*EE);
        #pragma unroll 8
        for (int idx = t; idx < 2048; idx += 256)
            edge_s[(idx >> 5)*33 + (idx & 31)] = eg[idx];
    }
    __syncthreads();

    // ---- Phase B: raw logits into lg (two 32-j halves) ----
    #pragma unroll
    for (int it = 0; it < 2; it++) {
        int jbase = it * 32;
        // B1: thread (jl = t&31, q = t>>5) covers g-range [q*4, q*4+4)
        {
            int jl = t & 31, q = t >> 5;
            float p[8] = {0,0,0,0,0,0,0,0};
            #pragma unroll
            for (int gg = 0; gg < 4; gg++) {
                int g = q*4 + gg;
                float4 e = edge_s[(jbase + jl)*33 + g];
                #pragma unroll
                for (int h = 0; h < 8; h++) {
                    float4 w = wb4[g*8 + h];
                    p[h] += e.x*w.x + e.y*w.y + e.z*w.z + e.w*w.w;
                }
            }
            #pragma unroll
            for (int h = 0; h < 8; h++) scratch[(q*32 + jl)*9 + h] = p[h];
        }
        __syncthreads();
        // B2: thread (jl = t&31, h = t>>5)
        {
            int jl = t & 31, h = t >> 5;
            float pb = 0.f;
            #pragma unroll
            for (int q = 0; q < 8; q++) pb += scratch[(q*32 + jl)*9 + h];
            int j = j0 + jbase + jl;
            float s = 0.f;
            #pragma unroll
            for (int k = 0; k < 16; k++)
                s += qs_s[h*16 + k] * g_kkT[(h*16 + k)*NN + j];
            float c = 0.f;
            #pragma unroll
            for (int k = 0; k < 12; k++)
                c += qp_s[h*12 + k] * g_kpT[(h*12 + k)*NN + j];
            float d = q2_s[h] + g_k2[h*NN + j] - 2.f*c;
            lg[h*64 + jbase + jl] =
                SCAL_SCALE*s - cw_s[h]*d + (pb + bb_s[h])*PAIR_SCALE;
        }
        __syncthreads();
    }

    // ---- Phase C: per-head chunk stats + exp; warp w = head w ----
    {
        int w = t >> 5, lane = t & 31;
        float v0 = lg[w*64 + lane], v1 = lg[w*64 + lane + 32];
        float m = fmaxf(v0, v1);
        #pragma unroll
        for (int s = 16; s > 0; s >>= 1) m = fmaxf(m, __shfl_xor_sync(0xffffffffu, m, s));
        float e0 = __expf(v0 - m), e1 = __expf(v1 - m);
        lg[w*64 + lane]      = e0;
        lg[w*64 + lane + 32] = e1;
        float cs = e0 + e1;
        #pragma unroll
        for (int s = 16; s > 0; s >>= 1) cs += __shfl_xor_sync(0xffffffffu, cs, s);
        g_attn[((size_t)w*NN + i)*NN + j0 + lane]      = e0;
        g_attn[((size_t)w*NN + i)*NN + j0 + lane + 32] = e1;
        if (lane == 0) {
            g_mc[w*(NN*8) + i*8 + jc] = m;
            g_sc[w*(NN*8) + i*8 + jc] = cs;
        }
    }
    __syncthreads();

    // ---- Phase D: rp partial from smem tile x lg ----
    {
        float4* red4 = (float4*)scratch;
        int e4 = t & 31, hh = (t >> 5) & 1, jg = t >> 6; // jg 0..3
        float4 acc[4];
        #pragma unroll
        for (int hl = 0; hl < 4; hl++) acc[hl] = make_float4(0.f,0.f,0.f,0.f);

        #pragma unroll 4
        for (int jj = 0; jj < 16; jj++) {
            int jrow = jg*16 + jj;
            float4 ev = edge_s[jrow*33 + e4];
            #pragma unroll
            for (int hl = 0; hl < 4; hl++) {
                float p = lg[(hh*4 + hl)*64 + jrow];
                acc[hl].x += ev.x*p; acc[hl].y += ev.y*p;
                acc[hl].z += ev.z*p; acc[hl].w += ev.w*p;
            }
        }
        if (jg >= 2) {
            #pragma unroll
            for (int hl = 0; hl < 4; hl++)
                red4[(((jg-2)*2 + hh)*4 + hl)*32 + e4] = acc[hl];
        }
        __syncthreads();
        if (jg < 2) {
            #pragma unroll
            for (int hl = 0; hl < 4; hl++) {
                float4 o = red4[((jg*2 + hh)*4 + hl)*32 + e4];
                acc[hl].x += o.x; acc[hl].y += o.y; acc[hl].z += o.z; acc[hl].w += o.w;
            }
        }
        __syncthreads();
        if (jg == 1) {
            #pragma unroll
            for (int hl = 0; hl < 4; hl++)
                red4[(hh*4 + hl)*32 + e4] = acc[hl];
        }
        __syncthreads();
        if (jg == 0) {
            float4* outp = (float4*)(g_rpp + ((size_t)jc*NN + i)*1024);
            #pragma unroll
            for (int hl = 0; hl < 4; hl++) {
                float4 o = red4[(hh*4 + hl)*32 + e4];
                outp[(hh*4 + hl)*32 + e4] = make_float4(acc[hl].x+o.x, acc[hl].y+o.y,
                                                        acc[hl].z+o.z, acc[hl].w+o.w);
            }
        }
    }
}

// ---------------------------------------------------------------------------
// kD: merge chunk stats; rs / pts / norms + rp reduction -> cat. grid 512.
// ---------------------------------------------------------------------------
__global__ void k_assemble(const float* __restrict__ rot,
                           const float* __restrict__ trans) {
    int i = blockIdx.x, t = threadIdx.x;
    __shared__ float at_s[8*512];
    __shared__ float rs_red[2*128];
    __shared__ float pt_red[2*96];
    __shared__ float pts_s[96];
    __shared__ float scl[8][8];   // [h][jc] = exp(m_c - m) / S

    if (t < 8) {
        int h = t;
        float mc[8], sc[8];
        float m = -1e30f;
        #pragma unroll
        for (int jc = 0; jc < 8; jc++) {
            mc[jc] = g_mc[h*(NN*8) + i*8 + jc];
            sc[jc] = g_sc[h*(NN*8) + i*8 + jc];
            m = fmaxf(m, mc[jc]);
        }
        float S = 0.f;
        #pragma unroll
        for (int jc = 0; jc < 8; jc++) {
            float e = __expf(mc[jc] - m);
            mc[jc] = e;
            S += sc[jc] * e;
        }
        float inv = 1.f / S;
        #pragma unroll
        for (int jc = 0; jc < 8; jc++) scl[h][jc] = mc[jc] * inv;
    }
    __syncthreads();

    for (int idx = t; idx < 4096; idx += 256) {
        int h = idx >> 9, j = idx & 511;
        at_s[idx] = g_attn[((size_t)h*NN + i)*NN + j] * scl[h][j >> 6];
    }
    __syncthreads();

    float* cat = &g_cat[(size_t)i*CATD];

    {
        int half = t >> 7, c = t & 127, h = c >> 4;
        float a = 0.f;
        #pragma unroll 8
        for (int j = 0; j < 256; j++)
            a += at_s[h*512 + half*256 + j] * g_vs[(size_t)(half*256 + j)*128 + c];
        rs_red[half*128 + c] = a;
    }
    if (t < 192) {
        int half = t / 96, q = t % 96, h = q / 12;
        float a = 0.f;
        #pragma unroll 8
        for (int j = 0; j < 256; j++)
            a += at_s[h*512 + half*256 + j] * g_vp[(size_t)(half*256 + j)*96 + q];
        pt_red[half*96 + q] = a;
    }
    for (int o = t; o < 1024; o += 256) {
        int h = o >> 7;
        float s = 0.f;
        #pragma unroll
        for (int jc = 0; jc < 8; jc++)
            s += g_rpp[((size_t)jc*NN + i)*1024 + o] * scl[h][jc];
        cat[256 + o] = s;
    }
    __syncthreads();
    if (t < 128) cat[t] = rs_red[t] + rs_red[128 + t];
    else if (t < 224) { int q = t - 128; pts_s[q] = pt_red[q] + pt_red[96 + q]; }
    __syncthreads();

    if (t < 32) {
        int base = t * 3;
        float T0 = trans[i*3], T1 = trans[i*3+1], T2 = trans[i*3+2];
        float x0 = pts_s[base] - T0, x1 = pts_s[base+1] - T1, x2 = pts_s[base+2] - T2;
        const float* R = &rot[i*9];
        float l0 = x0*R[0] + x1*R[1] + x2*R[2];
        float l1 = x0*R[3] + x1*R[4] + x2*R[5];
        float l2 = x0*R[6] + x1*R[7] + x2*R[8];
        cat[128 + base]     = l0;
        cat[128 + base + 1] = l1;
        cat[128 + base + 2] = l2;
        cat[224 + t] = sqrtf(l0*l0 + l1*l1 + l2*l2 + 1e-8f);
    }
}

// ---------------------------------------------------------------------------
// GEMM A (proj only): 32x32 tile, BK=32, 128 threads, 2x4 micro.
// ---------------------------------------------------------------------------
template<int LDX, int NC>
__global__ void k_gemm32(const float* __restrict__ X, const float* __restrict__ W,
                         const float* __restrict__ bias, float* __restrict__ Y, int klen) {
    int r0 = blockIdx.x * 32, c0 = blockIdx.y * 32;
    int t = threadIdx.x;
    __shared__ float Xs[32][33];
    __shared__ float Ws[32][36];

    int tx = t & 7, ty = t >> 3;
    int lrow = t >> 3, lkq = t & 7;

    float acc[2][4];
    #pragma unroll
    for (int a = 0; a < 2; a++)
        #pragma unroll
        for (int b = 0; b < 4; b++) acc[a][b] = 0.f;

    for (int kg = 0; kg < klen; kg += 32) {
        #pragma unroll
        for (int rr = 0; rr < 2; rr++) {
            int row = lrow + rr*16;
            float4 v = *(const float4*)&X[(size_t)(r0 + row)*LDX + kg + lkq*4];
            Xs[lkq*4 + 0][row] = v.x;
            Xs[lkq*4 + 1][row] = v.y;
            Xs[lkq*4 + 2][row] = v.z;
            Xs[lkq*4 + 3][row] = v.w;
        }
        #pragma unroll
        for (int rr = 0; rr < 2; rr++) {
            int k = lrow + rr*16;
            float4 v = *(const float4*)&W[(size_t)(kg + k)*NC + c0 + lkq*4];
            *(float4*)&Ws[k][lkq*4] = v;
        }
        __syncthreads();

        #pragma unroll
        for (int k = 0; k < 32; k++) {
            float x0 = Xs[k][ty*2 + 0];
            float x1 = Xs[k][ty*2 + 1];
            float4 wv = *(const float4*)&Ws[k][tx*4];
            acc[0][0] += x0*wv.x; acc[0][1] += x0*wv.y;
            acc[0][2] += x0*wv.z; acc[0][3] += x0*wv.w;
            acc[1][0] += x1*wv.x; acc[1][1] += x1*wv.y;
            acc[1][2] += x1*wv.z; acc[1][3] += x1*wv.w;
        }
        __syncthreads();
    }

    #pragma unroll
    for (int a = 0; a < 2; a++) {
        int row = r0 + ty*2 + a;
        #pragma unroll
        for (int b = 0; b < 4; b++) {
            int col = c0 + tx*4 + b;
            Y[(size_t)row*NC + col] = acc[a][b] + bias[col];
        }
    }
}

// ---------------------------------------------------------------------------
// GEMM B: 32x64 tile, BK=32, 128 threads, 4x4 micro. Split-K via blockIdx.z.
// ---------------------------------------------------------------------------
template<int LDX, int NC, bool RELU>
__global__ void k_gemm64(const float* __restrict__ X, const float* __restrict__ W,
                         const float* __restrict__ bias,
                         float* __restrict__ Y0, float* __restrict__ Y1,
                         float* __restrict__ Y2, float* __restrict__ Y3, int klen) {
    int r0 = blockIdx.x * 32, c0 = blockIdx.y * 64;
    int z = blockIdx.z;
    int kbase = z * klen;
    float* Y = (z == 0) ? Y0 : (z == 1) ? Y1 : (z == 2) ? Y2 : Y3;
    int t = threadIdx.x;
    __shared__ float Xs[32][36];
    __shared__ float Ws[32][68];

    int tx = t & 15, ty = t >> 4;

    float acc[4][4];
    #pragma unroll
    for (int a = 0; a < 4; a++)
        #pragma unroll
        for (int b = 0; b < 4; b++) acc[a][b] = 0.f;

    int xrow = t >> 2, xk4 = t & 3;
    for (int kc = 0; kc < klen; kc += 32) {
        int kg = kbase + kc;
        #pragma unroll
        for (int hh = 0; hh < 2; hh++) {
            int kq = xk4*2 + hh;
            float4 v = *(const float4*)&X[(size_t)(r0 + xrow)*LDX + kg + kq*4];
            Xs[kq*4 + 0][xrow] = v.x;
            Xs[kq*4 + 1][xrow] = v.y;
            Xs[kq*4 + 2][xrow] = v.z;
            Xs[kq*4 + 3][xrow] = v.w;
        }
        #pragma unroll
        for (int it = 0; it < 4; it++) {
            int idx = t + 128*it;
            int k = idx >> 4, cf4 = idx & 15;
            float4 v = *(const float4*)&W[(size_t)(kg + k)*NC + c0 + cf4*4];
            *(float4*)&Ws[k][cf4*4] = v;
        }
        __syncthreads();

        #pragma unroll
        for (int k = 0; k < 32; k++) {
            float4 xv = *(const float4*)&Xs[k][ty*4];
            float4 wv = *(const float4*)&Ws[k][tx*4];
            acc[0][0] += xv.x*wv.x; acc[0][1] += xv.x*wv.y; acc[0][2] += xv.x*wv.z; acc[0][3] += xv.x*wv.w;
            acc[1][0] += xv.y*wv.x; acc[1][1] += xv.y*wv.y; acc[1][2] += xv.y*wv.z; acc[1][3] += xv.y*wv.w;
            acc[2][0] += xv.z*wv.x; acc[2][1] += xv.z*wv.y; acc[2][2] += xv.z*wv.z; acc[2][3] += xv.z*wv.w;
            acc[3][0] += xv.w*wv.x; acc[3][1] += xv.w*wv.y; acc[3][2] += xv.w*wv.z; acc[3][3] += xv.w*wv.w;
        }
        __syncthreads();
    }

    #pragma unroll
    for (int a = 0; a < 4; a++) {
        int row = r0 + ty*4 + a;
        #pragma unroll
        for (int b = 0; b < 4; b++) {
            int col = c0 + tx*4 + b;
            float v = acc[a][b];
            if (z == 0) v += bias[col];
            if (RELU) v = fmaxf(v, 0.f);
            Y[(size_t)row*NC + col] = v;
        }
    }
}

// ---------------------------------------------------------------------------
// LayerNorm over 384 of (a+b+c+d). 128 threads, 3 elems each.
// ---------------------------------------------------------------------------
__global__ void k_ln4(const float* __restrict__ ia, const float* __restrict__ ib,
                      const float* __restrict__ ic, const float* __restrict__ id,
                      const float* __restrict__ g, const float* __restrict__ b,
                      float* __restrict__ out) {
    int i = blockIdx.x, t = threadIdx.x;
    __shared__ float red[128];
    float v0 = ia[i*DD+t]     + ib[i*DD+t]     + ic[i*DD+t]     + id[i*DD+t];
    float v1 = ia[i*DD+t+128] + ib[i*DD+t+128] + ic[i*DD+t+128] + id[i*DD+t+128];
    float v2 = ia[i*DD+t+256] + ib[i*DD+t+256] + ic[i*DD+t+256] + id[i*DD+t+256];
    red[t] = v0 + v1 + v2;
    __syncthreads();
    #pragma unroll
    for (int s = 64; s > 0; s >>= 1) { if (t < s) red[t] += red[t+s]; __syncthreads(); }
    float mu = red[0] * (1.f/384.f);
    __syncthreads();
    float d0 = v0-mu, d1 = v1-mu, d2 = v2-mu;
    red[t] = d0*d0 + d1*d1 + d2*d2;
    __syncthreads();
    #pragma unroll
    for (int s = 64; s > 0; s >>= 1) { if (t < s) red[t] += red[t+s]; __syncthreads(); }
    float inv = rsqrtf(red[0] * (1.f/384.f) + 1e-5f);
    out[i*DD + t]       = d0*inv*g[t]       + b[t];
    out[i*DD + t + 128] = d1*inv*g[t+128]   + b[t+128];
    out[i*DD + t + 256] = d2*inv*g[t+256]   + b[t+256];
}

// ---------------------------------------------------------------------------
extern "C" void kernel_launch(void* const* d_in, const int* in_sizes, int n_in,
                              void* d_out, int out_size) {
    const float* node  = (const float*)d_in[0];
    const float* edge  = (const float*)d_in[1];
    const float* rot   = (const float*)d_in[2];
    const float* trans = (const float*)d_in[3];
    const float* Wq_s = (const float*)d_in[5];
    const float* Wk_s = (const float*)d_in[6];
    const float* Wv_s = (const float*)d_in[7];
    const float* Wq_p = (const float*)d_in[8];
    const float* Wk_p = (const float*)d_in[9];
    const float* Wv_p = (const float*)d_in[10];
    const float* pw   = (const float*)d_in[11];
    const float* Wb   = (const float*)d_in[12];
    const float* bb   = (const float*)d_in[13];
    const float* Wo   = (const float*)d_in[14];
    const float* bo   = (const float*)d_in[15];
    const float* g1   = (const float*)d_in[16];
    const float* beta1= (const float*)d_in[17];
    const float* W1   = (const float*)d_in[18];
    const float* b1   = (const float*)d_in[19];
    const float* W2   = (const float*)d_in[20];
    const float* b2   = (const float*)d_in[21];
    const float* W3   = (const float*)d_in[22];
    const float* b3   = (const float*)d_in[23];
    const float* g2   = (const float*)d_in[24];
    const float* beta2= (const float*)d_in[25];
    float* out = (float*)d_out;

    float *p_cat, *p_t0, *p_t1, *p_t2, *p_t3, *p_x1, *p_h1, *p_h2;
    float *p_Wall, *p_zero, *p_proj;
    cudaGetSymbolAddress((void**)&p_cat, g_cat);
    cudaGetSymbolAddress((void**)&p_t0, g_t0);
    cudaGetSymbolAddress((void**)&p_t1, g_t1);
    cudaGetSymbolAddress((void**)&p_t2, g_t2);
    cudaGetSymbolAddress((void**)&p_t3, g_t3);
    cudaGetSymbolAddress((void**)&p_x1, g_x1);
    cudaGetSymbolAddress((void**)&p_h1, g_h1);
    cudaGetSymbolAddress((void**)&p_h2, g_h2);
    cudaGetSymbolAddress((void**)&p_Wall, g_Wall);
    cudaGetSymbolAddress((void**)&p_zero, g_zero);
    cudaGetSymbolAddress((void**)&p_proj, g_proj);

    k_packW<<<(DD*PCOLS + 255)/256, 256>>>(Wq_s, Wk_s, Wv_s, Wq_p, Wk_p, Wv_p);
    k_gemm32<DD, PCOLS><<<dim3(16, 21), 128>>>(node, p_Wall, p_zero, p_proj, DD);
    k_post<<<NN, 128>>>(rot, trans);
    k_fused<<<dim3(NN, 8), 256>>>(edge, Wb, bb, pw);
    k_assemble<<<NN, 256>>>(rot, trans);

    // Wo: split-K 4 x 320
    k_gemm64<CATD, DD, false><<<dim3(16, 6, 4), 128>>>(p_cat, Wo, bo, p_t0, p_t1, p_t2, p_t3, 320);
    k_ln4<<<NN, 128>>>(p_t0, p_t1, p_t2, p_t3, g1, beta1, p_x1);
    // MLP
    k_gemm64<DD, HID, true><<<dim3(16, 12, 1), 128>>>(p_x1, W1, b1, p_h1, p_h1, p_h1, p_h1, 384);
    k_gemm64<HID, HID, true><<<dim3(16, 12, 1), 128>>>(p_h1, W2, b2, p_h2, p_h2, p_h2, p_h2, 768);
    // W3: split-K 4 x 192
    k_gemm64<HID, DD, false><<<dim3(16, 6, 4), 128>>>(p_h2, W3, b3, p_t0, p_t1, p_t2, p_t3, 192);
    k_ln4<<<NN, 128>>>(p_t0, p_t1, p_t2, p_t3, g2, beta2, out);
}